// round 3
// baseline (speedup 1.0000x reference)
#include <cuda_runtime.h>
#include <cuda_bf16.h>

typedef unsigned int uint;

#define NTHR 256
#define NCTA 128

#define CHUNK_U4   6144u        // A-lo per (cell,ublk): 96 ksteps * 2 mtiles * 32 lanes
#define SEG_U4     4096u        // one B segment (K=512): 4 ntiles * 32 ksteps * 32 lanes
#define FCCHUNK_U4 4096u        // FC A chunk: 64 ksteps * 2 splits * 32 lanes

// SMEM: A-hi [2 cells][96 ksteps][2 mtiles][32 lanes] uint4 = 196608 B
//       sR   [8 warps][16 mrow][33] float                  =  16896 B
#define SA_BYTES   196608
#define SMEM_BYTES (SA_BYTES + 8 * 16 * 33 * 4)

// Static device scratch (allocation-free)
__device__ uint4 g_awlo[256u * CHUNK_U4];       // LSTM weight A-lo fragments  ~25MB
__device__ uint4 g_afcfrag[32u * FCCHUNK_U4];   // FC weight A fragments (hi|lo) ~2MB
__device__ uint4 g_xfrag[512ull * SEG_U4];      // input x B-fragments, all t  ~32MB
__device__ uint4 g_hfrag[8u * SEG_U4];          // h B-fragments [parity][cell]
__device__ uint4 g_pfrag[SEG_U4];               // prev-pred B-fragments
__device__ unsigned g_arrive  = 0;
__device__ unsigned g_release = 0;

// ---------------- grid barrier (monotonic ticket; 128 CTAs <= #SMs) ----------
__device__ __forceinline__ void gridbar() {
    __syncthreads();
    if (threadIdx.x == 0) {
        __threadfence();
        const unsigned nb = gridDim.x;
        unsigned ticket = atomicAdd(&g_arrive, 1u);
        if (ticket % nb == nb - 1u) {
            atomicAdd(&g_release, nb);
        } else {
            volatile unsigned* rel = &g_release;
            while ((int)(*rel - ticket) <= 0) __nanosleep(32);
        }
        __threadfence();
    }
    __syncthreads();
}

__device__ __forceinline__ float sigf(float v) { return 1.0f / (1.0f + expf(-v)); }

// ---------------- bf16 split helpers ----------------------------------------
__device__ __forceinline__ void split_pair(float a, float b, uint& hi, uint& lo) {
    __nv_bfloat16 ha = __float2bfloat16(a), hb = __float2bfloat16(b);
    float ra = a - __bfloat162float(ha);
    float rb = b - __bfloat162float(hb);
    __nv_bfloat16 la = __float2bfloat16(ra), lb = __float2bfloat16(rb);
    hi = (uint)__bfloat16_as_ushort(ha) | ((uint)__bfloat16_as_ushort(hb) << 16);
    lo = (uint)__bfloat16_as_ushort(la) | ((uint)__bfloat16_as_ushort(lb) << 16);
}

// Write one activation value (k,n) into B-fragment slots (hi and lo halves).
__device__ __forceinline__ void write_bfrag(uint4* base, int k, int n, float v) {
    __nv_bfloat16 hi = __float2bfloat16(v);
    float rem = v - __bfloat162float(hi);
    __nv_bfloat16 lo = __float2bfloat16(rem);
    int ks = k >> 4, kk = k & 15, nt = n >> 3;
    int tp  = ((n & 7) << 2) | ((kk >> 1) & 3);
    int reg = kk >> 3;
    int half = kk & 1;
    char* p = (char*)(base + ((size_t)(nt * 32 + ks) * 32 + tp));
    *(__nv_bfloat16*)(p + reg * 4 + half * 2)     = hi;
    *(__nv_bfloat16*)(p + 8 + reg * 4 + half * 2) = lo;
}

// ---------------- mma.sync m16n8k16 bf16 -> fp32 -----------------------------
struct Acc { float x, y, z, w; };

__device__ __forceinline__ void mma_bf16(Acc& c, uint4 a, uint b0, uint b1) {
    asm volatile(
        "mma.sync.aligned.m16n8k16.row.col.f32.bf16.bf16.f32 "
        "{%0,%1,%2,%3}, {%4,%5,%6,%7}, {%8,%9}, {%0,%1,%2,%3};"
        : "+f"(c.x), "+f"(c.y), "+f"(c.z), "+f"(c.w)
        : "r"(a.x), "r"(a.y), "r"(a.z), "r"(a.w), "r"(b0), "r"(b1));
}

// One LSTM phase. Warp w: mtile = w&1, ksplit = w>>1 (24 ksteps of 96).
// Each warp covers N=32 (4 ntiles) with 12 accumulators; A loaded once/kstep.
__device__ __forceinline__ void lstm_phase(
    const uint4* __restrict__ sA,      // SMEM A-hi for this cell [96][2][32]
    float* sR,                          // SMEM reduce buffer [8][16][33]
    const uint4* __restrict__ alo,     // global A-lo chunk for this cell
    const uint4* __restrict__ segB0,
    const uint4* __restrict__ segB1,
    const uint4* __restrict__ segB2,
    const float* __restrict__ bihc, const float* __restrict__ bhhc,
    float& creg, float& hreg, uint4* hout, int j0)
{
    const int tid  = threadIdx.x;
    const int lane = tid & 31;
    const int w    = tid >> 5;
    const int mtile = w & 1;
    const int ks0   = (w >> 1) * 24;

    Acc a0={0,0,0,0},a1={0,0,0,0},a2={0,0,0,0},a3={0,0,0,0};
    Acc b0a={0,0,0,0},b1a={0,0,0,0},b2a={0,0,0,0},b3a={0,0,0,0};
    Acc c0a={0,0,0,0},c1a={0,0,0,0},c2a={0,0,0,0},c3a={0,0,0,0};

    #pragma unroll 4
    for (int k = 0; k < 24; ++k) {
        int kk  = ks0 + k;
        int s   = kk >> 5;
        int kin = kk & 31;
        const uint4* B = (s == 0 ? segB0 : (s == 1 ? segB1 : segB2)) + kin * 32 + lane;
        uint4 v0 = __ldg(B);
        uint4 v1 = __ldg(B + 1024);
        uint4 v2 = __ldg(B + 2048);
        uint4 v3 = __ldg(B + 3072);
        uint4 ah = sA[(kk * 2 + mtile) * 32 + lane];
        uint4 al = __ldg(alo + (kk * 2 + mtile) * 32 + lane);
        mma_bf16(a0, ah, v0.x, v0.y);
        mma_bf16(a1, ah, v1.x, v1.y);
        mma_bf16(a2, ah, v2.x, v2.y);
        mma_bf16(a3, ah, v3.x, v3.y);
        mma_bf16(b0a, ah, v0.z, v0.w);
        mma_bf16(b1a, ah, v1.z, v1.w);
        mma_bf16(b2a, ah, v2.z, v2.w);
        mma_bf16(b3a, ah, v3.z, v3.w);
        mma_bf16(c0a, al, v0.x, v0.y);
        mma_bf16(c1a, al, v1.x, v1.y);
        mma_bf16(c2a, al, v2.x, v2.y);
        mma_bf16(c3a, al, v3.x, v3.y);
    }

    // combine splits and store partials: sR[w][mrow][n]
    const int gid = lane >> 2, tig = lane & 3;
    float* r = sR + w * (16 * 33);
    {
        Acc t;
        t.x=a0.x+b0a.x+c0a.x; t.y=a0.y+b0a.y+c0a.y; t.z=a0.z+b0a.z+c0a.z; t.w=a0.w+b0a.w+c0a.w;
        int n0 = 0*8 + tig*2;
        r[gid*33+n0]=t.x; r[gid*33+n0+1]=t.y; r[(gid+8)*33+n0]=t.z; r[(gid+8)*33+n0+1]=t.w;
        t.x=a1.x+b1a.x+c1a.x; t.y=a1.y+b1a.y+c1a.y; t.z=a1.z+b1a.z+c1a.z; t.w=a1.w+b1a.w+c1a.w;
        n0 = 1*8 + tig*2;
        r[gid*33+n0]=t.x; r[gid*33+n0+1]=t.y; r[(gid+8)*33+n0]=t.z; r[(gid+8)*33+n0+1]=t.w;
        t.x=a2.x+b2a.x+c2a.x; t.y=a2.y+b2a.y+c2a.y; t.z=a2.z+b2a.z+c2a.z; t.w=a2.w+b2a.w+c2a.w;
        n0 = 2*8 + tig*2;
        r[gid*33+n0]=t.x; r[gid*33+n0+1]=t.y; r[(gid+8)*33+n0]=t.z; r[(gid+8)*33+n0+1]=t.w;
        t.x=a3.x+b3a.x+c3a.x; t.y=a3.y+b3a.y+c3a.y; t.z=a3.z+b3a.z+c3a.z; t.w=a3.w+b3a.w+c3a.w;
        n0 = 3*8 + tig*2;
        r[gid*33+n0]=t.x; r[gid*33+n0+1]=t.y; r[(gid+8)*33+n0]=t.z; r[(gid+8)*33+n0+1]=t.w;
    }
    __syncthreads();

    // pointwise: thread = (unit ul, batch b). gate rows m = ul*4 + gate.
    const int ul = tid >> 5, b = tid & 31;
    const int j = j0 + ul;
    float g4[4];
    #pragma unroll
    for (int g = 0; g < 4; ++g) {
        int m = ul * 4 + g, mt = m >> 4, mr = m & 15;
        float s = 0.f;
        #pragma unroll
        for (int ks = 0; ks < 4; ++ks)
            s += sR[(ks * 2 + mt) * (16 * 33) + mr * 33 + b];
        g4[g] = s;
    }
    float gi = g4[0] + __ldg(bihc + j)        + __ldg(bhhc + j);
    float gf = g4[1] + __ldg(bihc + j +  512) + __ldg(bhhc + j +  512);
    float gg = g4[2] + __ldg(bihc + j + 1024) + __ldg(bhhc + j + 1024);
    float go = g4[3] + __ldg(bihc + j + 1536) + __ldg(bhhc + j + 1536);
    float cc = sigf(gf) * creg + sigf(gi) * tanhf(gg);
    creg = cc;
    hreg = sigf(go) * tanhf(cc);
    write_bfrag(hout, j, b, hreg);
}

// -----------------------------------------------------------------------------
extern "C" __global__ void __launch_bounds__(NTHR, 1)
ar_encoder_mma3(const float* __restrict__ x,     // [32,512,512]
                const float* __restrict__ Wih,   // [4][2048][1024]
                const float* __restrict__ Whh,   // [4][2048][512]
                const float* __restrict__ bih,   // [4][2048]
                const float* __restrict__ bhh,   // [4][2048]
                const float* __restrict__ Wfc,   // [512][1024]
                const float* __restrict__ bfc,   // [512]
                float* __restrict__ out)
{
    extern __shared__ char smem[];
    uint4* sA = (uint4*)smem;                       // [2][96][2][32]
    float* sR = (float*)(smem + SA_BYTES);          // [8][16][33]

    const int tid  = threadIdx.x;
    const int cta  = blockIdx.x;
    const int lane = tid & 31;
    const int wrp  = tid >> 5;
    const int gsz  = NCTA * NTHR;
    const int gtid = cta * NTHR + tid;

    const int d    = cta >> 6;
    const int ublk = cta & 63;
    const int j0   = ublk * 8;

    // ================= prologue =============================================
    // (1) this CTA's LSTM weights: hi -> SMEM, lo -> global chunk
    for (int i = tid; i < 2 * 32 * 768; i += NTHR) {
        int kp = i % 768;
        int rm = i / 768;               // 0..63
        int m  = rm & 31;
        int ci = rm >> 5;               // 0 = layer0 cell, 1 = layer1 cell
        int cell = (ci == 0) ? d : (2 + d);
        int ulp = m >> 2, gp = m & 3;
        int row = gp * 512 + j0 + ulp;
        int k = kp * 2;
        float w0, w1;
        if (k < 1024) {
            const float* p = Wih + ((size_t)cell * 2048 + row) * 1024 + k;
            w0 = p[0]; w1 = p[1];
        } else {
            const float* p = Whh + ((size_t)cell * 2048 + row) * 512 + (k - 1024);
            w0 = p[0]; w1 = p[1];
        }
        uint hi, lo; split_pair(w0, w1, hi, lo);
        int kstep = k >> 4, kk = k & 15;
        int mtile = m >> 4, mrow = m & 15;
        int tp  = ((mrow & 7) << 2) | ((kk >> 1) & 3);
        int reg = (mrow >> 3) | ((kk >> 3) << 1);
        ((uint*)sA)[ ((((ci * 96 + kstep) * 2 + mtile) * 32) + tp) * 4 + reg ] = hi;
        ((uint*)(g_awlo + (size_t)(cell * 64 + ublk) * CHUNK_U4))
            [ (((kstep * 2 + mtile) * 32) + tp) * 4 + reg ] = lo;
    }
    // (2) FC weights -> A fragments (hi|lo), grid-strided
    for (uint i = gtid; i < 512u * 512u; i += gsz) {
        int kp = (int)(i & 511u), row = (int)(i >> 9);
        int k = kp * 2;
        const float* p = Wfc + ((size_t)row << 10) + k;
        uint hi, lo; split_pair(p[0], p[1], hi, lo);
        int rowblk = row >> 4, mrow = row & 15;
        int kstep = k >> 4, kk = k & 15;
        int tp  = ((mrow & 7) << 2) | ((kk >> 1) & 3);
        int reg = (mrow >> 3) | ((kk >> 3) << 1);
        ((uint*)(g_afcfrag + (size_t)rowblk * FCCHUNK_U4 + (size_t)kstep * 64 + tp))[reg] = hi;
        ((uint*)(g_afcfrag + (size_t)rowblk * FCCHUNK_U4 + (size_t)kstep * 64 + 32 + tp))[reg] = lo;
    }
    // (3) input x -> B fragments for all 512 steps
    for (size_t s = gtid; s < 512ull * SEG_U4; s += gsz) {
        int ln = (int)(s & 31), ks = (int)((s >> 5) & 31), nt = (int)((s >> 10) & 3);
        int t  = (int)(s >> 12);
        int tig = ln & 3, gid = ln >> 2;
        int n = nt * 8 + gid, k0 = ks * 16 + tig * 2;
        const float* xp = x + ((size_t)n * 512 + t) * 512 + k0;
        float q0 = xp[0], q1 = xp[1], q2 = xp[8], q3 = xp[9];
        uint4 v;
        split_pair(q0, q1, v.x, v.z);
        split_pair(q2, q3, v.y, v.w);
        g_xfrag[s] = v;
    }
    // (4) zero parity-0 h fragments + prev fragments
    {
        uint4 z = make_uint4(0, 0, 0, 0);
        for (uint i = gtid; i < 5u * SEG_U4; i += gsz) {
            if (i < 4u * SEG_U4) g_hfrag[i] = z;
            else                 g_pfrag[i - 4u * SEG_U4] = z;
        }
    }
    gridbar();

    // ================= main autoregressive loop ==============================
    float creg0 = 0.f, hreg0 = 0.f, creg1 = 0.f, hreg1 = 0.f;
    const uint4* alo0 = g_awlo + (size_t)((0 + d) * 64 + ublk) * CHUNK_U4;
    const uint4* alo1 = g_awlo + (size_t)((2 + d) * 64 + ublk) * CHUNK_U4;

    for (int t = 0; t < 512; ++t) {
        const int pold = t & 1, pnew = pold ^ 1;

        // ---- layer 0 (cell = d): B = [x_t | prev | h_old] ----
        lstm_phase(sA, sR, alo0,
                   g_xfrag + (size_t)t * SEG_U4,
                   g_pfrag,
                   g_hfrag + (size_t)(pold * 4 + d) * SEG_U4,
                   bih + (size_t)d * 2048, bhh + (size_t)d * 2048,
                   creg0, hreg0,
                   g_hfrag + (size_t)(pnew * 4 + d) * SEG_U4, j0);
        gridbar();

        // ---- layer 1 (cell = 2+d): B = [h0_new | h1_new | h_old] ----
        lstm_phase(sA + 96 * 2 * 32, sR, alo1,
                   g_hfrag + (size_t)(pnew * 4 + 0) * SEG_U4,
                   g_hfrag + (size_t)(pnew * 4 + 1) * SEG_U4,
                   g_hfrag + (size_t)(pold * 4 + 2 + d) * SEG_U4,
                   bih + (size_t)(2 + d) * 2048, bhh + (size_t)(2 + d) * 2048,
                   creg1, hreg1,
                   g_hfrag + (size_t)(pnew * 4 + 2 + d) * SEG_U4, j0);
        gridbar();

        // ---- FC head on CTAs 0..31: 16 rows each, 8 K-split warps ----
        if (cta < 32) {
            const uint4* A = g_afcfrag + (size_t)cta * FCCHUNK_U4;
            const uint4* segB = g_hfrag + (size_t)(pnew * 4 + 2 + (wrp >> 2)) * SEG_U4;
            const int kbase = (wrp * 8) & 31;

            Acc a0={0,0,0,0},a1={0,0,0,0},a2={0,0,0,0},a3={0,0,0,0};
            Acc b0a={0,0,0,0},b1a={0,0,0,0},b2a={0,0,0,0},b3a={0,0,0,0};
            Acc c0a={0,0,0,0},c1a={0,0,0,0},c2a={0,0,0,0},c3a={0,0,0,0};
            #pragma unroll
            for (int k = 0; k < 8; ++k) {
                int kk  = wrp * 8 + k;
                int kin = kbase + k;
                const uint4* B = segB + kin * 32 + lane;
                uint4 v0 = __ldg(B);
                uint4 v1 = __ldg(B + 1024);
                uint4 v2 = __ldg(B + 2048);
                uint4 v3 = __ldg(B + 3072);
                uint4 ah = __ldg(A + (size_t)kk * 64 + lane);
                uint4 al = __ldg(A + (size_t)kk * 64 + 32 + lane);
                mma_bf16(a0, ah, v0.x, v0.y);
                mma_bf16(a1, ah, v1.x, v1.y);
                mma_bf16(a2, ah, v2.x, v2.y);
                mma_bf16(a3, ah, v3.x, v3.y);
                mma_bf16(b0a, ah, v0.z, v0.w);
                mma_bf16(b1a, ah, v1.z, v1.w);
                mma_bf16(b2a, ah, v2.z, v2.w);
                mma_bf16(b3a, ah, v3.z, v3.w);
                mma_bf16(c0a, al, v0.x, v0.y);
                mma_bf16(c1a, al, v1.x, v1.y);
                mma_bf16(c2a, al, v2.x, v2.y);
                mma_bf16(c3a, al, v3.x, v3.y);
            }
            const int gid = lane >> 2, tig = lane & 3;
            float* r = sR + wrp * (16 * 33);
            {
                float t0,t1,t2,t3; int n0;
                t0=a0.x+b0a.x+c0a.x; t1=a0.y+b0a.y+c0a.y; t2=a0.z+b0a.z+c0a.z; t3=a0.w+b0a.w+c0a.w;
                n0 = 0 + tig*2;
                r[gid*33+n0]=t0; r[gid*33+n0+1]=t1; r[(gid+8)*33+n0]=t2; r[(gid+8)*33+n0+1]=t3;
                t0=a1.x+b1a.x+c1a.x; t1=a1.y+b1a.y+c1a.y; t2=a1.z+b1a.z+c1a.z; t3=a1.w+b1a.w+c1a.w;
                n0 = 8 + tig*2;
                r[gid*33+n0]=t0; r[gid*33+n0+1]=t1; r[(gid+8)*33+n0]=t2; r[(gid+8)*33+n0+1]=t3;
                t0=a2.x+b2a.x+c2a.x; t1=a2.y+b2a.y+c2a.y; t2=a2.z+b2a.z+c2a.z; t3=a2.w+b2a.w+c2a.w;
                n0 = 16 + tig*2;
                r[gid*33+n0]=t0; r[gid*33+n0+1]=t1; r[(gid+8)*33+n0]=t2; r[(gid+8)*33+n0+1]=t3;
                t0=a3.x+b3a.x+c3a.x; t1=a3.y+b3a.y+c3a.y; t2=a3.z+b3a.z+c3a.z; t3=a3.w+b3a.w+c3a.w;
                n0 = 24 + tig*2;
                r[gid*33+n0]=t0; r[gid*33+n0+1]=t1; r[(gid+8)*33+n0]=t2; r[(gid+8)*33+n0+1]=t3;
            }
            __syncthreads();
            const int rr = tid >> 5, b = tid & 31;
            #pragma unroll
            for (int hh = 0; hh < 2; ++hh) {
                int mr  = rr + hh * 8;
                int row = cta * 16 + mr;
                float v = __ldg(bfc + row);
                #pragma unroll
                for (int w2 = 0; w2 < 8; ++w2)
                    v += sR[w2 * (16 * 33) + mr * 33 + b];
                out[((size_t)b * 512 + t) * 512 + row] = v;
                write_bfrag(g_pfrag, row, b, v);
            }
        }
        gridbar();
    }

    // ================= epilogue: h_n, c_n from registers =====================
    {
        const size_t HN = 8388608ull;             // 32*512*512
        const size_t CN = HN + 65536ull;
        int ul = tid >> 5, b = tid & 31;
        int j = j0 + ul;
        out[HN + ((size_t)((0 + d) * 32 + b)) * 512 + j] = hreg0;
        out[HN + ((size_t)((2 + d) * 32 + b)) * 512 + j] = hreg1;
        out[CN + ((size_t)((0 + d) * 32 + b)) * 512 + j] = creg0;
        out[CN + ((size_t)((2 + d) * 32 + b)) * 512 + j] = creg1;
    }
}

extern "C" void kernel_launch(void* const* d_in, const int* in_sizes, int n_in,
                              void* d_out, int out_size) {
    (void)in_sizes; (void)n_in; (void)out_size;
    const float* x   = (const float*)d_in[0];
    const float* Wih = (const float*)d_in[2];
    const float* Whh = (const float*)d_in[3];
    const float* bih = (const float*)d_in[4];
    const float* bhh = (const float*)d_in[5];
    const float* Wfc = (const float*)d_in[6];
    const float* bfc = (const float*)d_in[7];
    cudaFuncSetAttribute(ar_encoder_mma3,
                         cudaFuncAttributeMaxDynamicSharedMemorySize, SMEM_BYTES);
    ar_encoder_mma3<<<NCTA, NTHR, SMEM_BYTES>>>(x, Wih, Whh, bih, bhh, Wfc, bfc,
                                                (float*)d_out);
}

// round 4
// speedup vs baseline: 1.6092x; 1.6092x over previous
#include <cuda_runtime.h>
#include <cuda_bf16.h>

typedef unsigned int uint;

#define NTHR 384
#define NCTA 128

#define CHUNK_U4   6144u        // A-lo per (cell,ublk): 96 ksteps * 2 mtiles * 32 lanes
#define SEG_U4     4096u        // one B segment (K=512): 4 ntiles * 32 ksteps * 32 lanes
#define FCCHUNK_U4 4096u        // FC A chunk: 64 ksteps * 2 splits * 32 lanes

// SMEM: A-hi [2 cells][96 ksteps][2 mtiles][32 lanes] uint4 = 196608 B
//       sR   [3 kthirds][32 mrow][33] float             =  12672 B
#define SA_BYTES   196608
#define SR_FLOATS  (3 * 32 * 33)
#define SMEM_BYTES (SA_BYTES + SR_FLOATS * 4)

// Static device scratch (allocation-free)
__device__ uint4 g_awlo[256u * CHUNK_U4];       // LSTM weight A-lo fragments  ~25MB
__device__ uint4 g_afcfrag[32u * FCCHUNK_U4];   // FC weight A fragments (hi|lo)
__device__ uint4 g_xfrag[512ull * SEG_U4];      // input x B-fragments, all t  ~32MB
__device__ uint4 g_hfrag[8u * SEG_U4];          // h B-fragments [parity][cell]
__device__ uint4 g_pfrag[SEG_U4];               // prev-pred B-fragments
__device__ unsigned g_arrive  = 0;
__device__ unsigned g_release = 0;

// ---------------- grid barrier (monotonic ticket; 128 CTAs <= #SMs) ----------
__device__ __forceinline__ void gridbar() {
    __syncthreads();
    if (threadIdx.x == 0) {
        __threadfence();
        const unsigned nb = gridDim.x;
        unsigned ticket = atomicAdd(&g_arrive, 1u);
        if (ticket % nb == nb - 1u) {
            atomicAdd(&g_release, nb);
        } else {
            volatile unsigned* rel = &g_release;
            while ((int)(*rel - ticket) <= 0) __nanosleep(32);
        }
        __threadfence();
    }
    __syncthreads();
}

__device__ __forceinline__ float sigf(float v) { return 1.0f / (1.0f + expf(-v)); }

// ---------------- bf16 split helpers ----------------------------------------
__device__ __forceinline__ void split_pair(float a, float b, uint& hi, uint& lo) {
    __nv_bfloat16 ha = __float2bfloat16(a), hb = __float2bfloat16(b);
    float ra = a - __bfloat162float(ha);
    float rb = b - __bfloat162float(hb);
    __nv_bfloat16 la = __float2bfloat16(ra), lb = __float2bfloat16(rb);
    hi = (uint)__bfloat16_as_ushort(ha) | ((uint)__bfloat16_as_ushort(hb) << 16);
    lo = (uint)__bfloat16_as_ushort(la) | ((uint)__bfloat16_as_ushort(lb) << 16);
}

// Write one activation value (k,n) into B-fragment slots (hi and lo halves).
__device__ __forceinline__ void write_bfrag(uint4* base, int k, int n, float v) {
    __nv_bfloat16 hi = __float2bfloat16(v);
    float rem = v - __bfloat162float(hi);
    __nv_bfloat16 lo = __float2bfloat16(rem);
    int ks = k >> 4, kk = k & 15, nt = n >> 3;
    int tp  = ((n & 7) << 2) | ((kk >> 1) & 3);
    int reg = kk >> 3;
    int half = kk & 1;
    char* p = (char*)(base + ((size_t)(nt * 32 + ks) * 32 + tp));
    *(__nv_bfloat16*)(p + reg * 4 + half * 2)     = hi;
    *(__nv_bfloat16*)(p + 8 + reg * 4 + half * 2) = lo;
}

// ---------------- mma.sync m16n8k16 bf16 -> fp32 -----------------------------
struct Acc { float x, y, z, w; };

__device__ __forceinline__ void mma_bf16(Acc& c, uint4 a, uint b0, uint b1) {
    asm volatile(
        "mma.sync.aligned.m16n8k16.row.col.f32.bf16.bf16.f32 "
        "{%0,%1,%2,%3}, {%4,%5,%6,%7}, {%8,%9}, {%0,%1,%2,%3};"
        : "+f"(c.x), "+f"(c.y), "+f"(c.z), "+f"(c.w)
        : "r"(c.x=c.x,a.x), "r"(a.y), "r"(a.z), "r"(a.w), "r"(b0), "r"(b1));
}

// store one Acc sum into reduce buffer at (m0 rows, n0 cols)
__device__ __forceinline__ void stacc(float* r, int m0, int n0, Acc A, Acc Bq, Acc C) {
    r[m0 * 33 + n0]           = A.x + Bq.x + C.x;
    r[m0 * 33 + n0 + 1]       = A.y + Bq.y + C.y;
    r[(m0 + 8) * 33 + n0]     = A.z + Bq.z + C.z;
    r[(m0 + 8) * 33 + n0 + 1] = A.w + Bq.w + C.w;
}

// One LSTM phase. 12 warps: mtile = w&1, npair = (w>>1)&1, kthird = w>>2.
// Each warp: one 32-kstep segment, N=16 (2 ntiles), 6 accumulators.
__device__ __forceinline__ void lstm_phase(
    const uint4* __restrict__ sA,      // SMEM A-hi for this cell [96][2][32]
    float* sR,                          // SMEM reduce buffer [3][32][33]
    const uint4* __restrict__ alo,     // global A-lo chunk for this cell
    const uint4* __restrict__ segB0,
    const uint4* __restrict__ segB1,
    const uint4* __restrict__ segB2,
    const float* __restrict__ bihc, const float* __restrict__ bhhc,
    float& creg, float& hreg, uint4* hout, int j0)
{
    const int tid   = threadIdx.x;
    const int lane  = tid & 31;
    const int w     = tid >> 5;
    const int mtile = w & 1;
    const int npair = (w >> 1) & 1;
    const int kthird = w >> 2;          // 0..2

    const uint4* B = (kthird == 0 ? segB0 : (kthird == 1 ? segB1 : segB2))
                     + npair * 2048 + lane;
    const uint4* Ah = sA  + (kthird * 64 + mtile) * 32 + lane;
    const uint4* Al = alo + (kthird * 64 + mtile) * 32 + lane;

    Acc p0={0,0,0,0}, p1={0,0,0,0}, p2={0,0,0,0};
    Acc q0={0,0,0,0}, q1={0,0,0,0}, q2={0,0,0,0};

    #pragma unroll 8
    for (int k = 0; k < 32; ++k) {
        uint4 v0 = B[k * 32];           // ntile npair*2   (hi: x,y  lo: z,w)
        uint4 v1 = B[k * 32 + 1024];    // ntile npair*2+1
        uint4 ah = Ah[k * 64];          // SMEM
        uint4 al = __ldg(Al + k * 64);  // global (L2)
        mma_bf16(p0, ah, v0.x, v0.y);
        mma_bf16(q0, ah, v1.x, v1.y);
        mma_bf16(p1, ah, v0.z, v0.w);
        mma_bf16(q1, ah, v1.z, v1.w);
        mma_bf16(p2, al, v0.x, v0.y);
        mma_bf16(q2, al, v1.x, v1.y);
    }

    const int gid = lane >> 2, tig = lane & 3;
    float* r = sR + kthird * (32 * 33);
    const int m0 = mtile * 16 + gid;
    stacc(r, m0, npair * 16 + tig * 2,     p0, p1, p2);
    stacc(r, m0, npair * 16 + 8 + tig * 2, q0, q1, q2);
    __syncthreads();

    // pointwise (first 256 threads): thread = (unit ul, batch b)
    if (tid < 256) {
        const int ul = tid >> 5, b = tid & 31;
        const int j = j0 + ul;
        float g4[4];
        #pragma unroll
        for (int g = 0; g < 4; ++g) {
            int m = ul * 4 + g;
            g4[g] = sR[m * 33 + b] + sR[(32*33) + m * 33 + b] + sR[2*(32*33) + m * 33 + b];
        }
        float gi = g4[0] + __ldg(bihc + j)        + __ldg(bhhc + j);
        float gf = g4[1] + __ldg(bihc + j +  512) + __ldg(bhhc + j +  512);
        float gg = g4[2] + __ldg(bihc + j + 1024) + __ldg(bhhc + j + 1024);
        float go = g4[3] + __ldg(bihc + j + 1536) + __ldg(bhhc + j + 1536);
        float cc = sigf(gf) * creg + sigf(gi) * tanhf(gg);
        creg = cc;
        hreg = sigf(go) * tanhf(cc);
        write_bfrag(hout, j, b, hreg);
    }
}

// -----------------------------------------------------------------------------
extern "C" __global__ void __launch_bounds__(NTHR, 1)
ar_encoder_mma4(const float* __restrict__ x,     // [32,512,512]
                const float* __restrict__ Wih,   // [4][2048][1024]
                const float* __restrict__ Whh,   // [4][2048][512]
                const float* __restrict__ bih,   // [4][2048]
                const float* __restrict__ bhh,   // [4][2048]
                const float* __restrict__ Wfc,   // [512][1024]
                const float* __restrict__ bfc,   // [512]
                float* __restrict__ out)
{
    extern __shared__ char smem[];
    uint4* sA = (uint4*)smem;                       // [2][96][2][32]
    float* sR = (float*)(smem + SA_BYTES);          // [3][32][33]

    const int tid  = threadIdx.x;
    const int cta  = blockIdx.x;
    const int lane = tid & 31;
    const int wrp  = tid >> 5;
    const int gsz  = NCTA * NTHR;
    const int gtid = cta * NTHR + tid;

    const int d    = cta >> 6;
    const int ublk = cta & 63;
    const int j0   = ublk * 8;

    // ================= prologue =============================================
    // (1) this CTA's LSTM weights: hi -> SMEM, lo -> global chunk
    for (int i = tid; i < 2 * 32 * 768; i += NTHR) {
        int kp = i % 768;
        int rm = i / 768;
        int m  = rm & 31;
        int ci = rm >> 5;
        int cell = (ci == 0) ? d : (2 + d);
        int ulp = m >> 2, gp = m & 3;
        int row = gp * 512 + j0 + ulp;
        int k = kp * 2;
        float w0, w1;
        if (k < 1024) {
            const float* p = Wih + ((size_t)cell * 2048 + row) * 1024 + k;
            w0 = p[0]; w1 = p[1];
        } else {
            const float* p = Whh + ((size_t)cell * 2048 + row) * 512 + (k - 1024);
            w0 = p[0]; w1 = p[1];
        }
        uint hi, lo; split_pair(w0, w1, hi, lo);
        int kstep = k >> 4, kk = k & 15;
        int mtile = m >> 4, mrow = m & 15;
        int tp  = ((mrow & 7) << 2) | ((kk >> 1) & 3);
        int reg = (mrow >> 3) | ((kk >> 3) << 1);
        ((uint*)sA)[ ((((ci * 96 + kstep) * 2 + mtile) * 32) + tp) * 4 + reg ] = hi;
        ((uint*)(g_awlo + (size_t)(cell * 64 + ublk) * CHUNK_U4))
            [ (((kstep * 2 + mtile) * 32) + tp) * 4 + reg ] = lo;
    }
    // (2) FC weights -> A fragments (hi|lo), grid-strided
    for (uint i = gtid; i < 512u * 512u; i += gsz) {
        int kp = (int)(i & 511u), row = (int)(i >> 9);
        int k = kp * 2;
        const float* p = Wfc + ((size_t)row << 10) + k;
        uint hi, lo; split_pair(p[0], p[1], hi, lo);
        int rowblk = row >> 4, mrow = row & 15;
        int kstep = k >> 4, kk = k & 15;
        int tp  = ((mrow & 7) << 2) | ((kk >> 1) & 3);
        int reg = (mrow >> 3) | ((kk >> 3) << 1);
        ((uint*)(g_afcfrag + (size_t)rowblk * FCCHUNK_U4 + (size_t)kstep * 64 + tp))[reg] = hi;
        ((uint*)(g_afcfrag + (size_t)rowblk * FCCHUNK_U4 + (size_t)kstep * 64 + 32 + tp))[reg] = lo;
    }
    // (3) input x -> B fragments for all 512 steps
    for (size_t s = gtid; s < 512ull * SEG_U4; s += gsz) {
        int ln = (int)(s & 31), ks = (int)((s >> 5) & 31), nt = (int)((s >> 10) & 3);
        int t  = (int)(s >> 12);
        int tig = ln & 3, gid = ln >> 2;
        int n = nt * 8 + gid, k0 = ks * 16 + tig * 2;
        const float* xp = x + ((size_t)n * 512 + t) * 512 + k0;
        float q0 = xp[0], q1 = xp[1], q2 = xp[8], q3 = xp[9];
        uint4 v;
        split_pair(q0, q1, v.x, v.z);
        split_pair(q2, q3, v.y, v.w);
        g_xfrag[s] = v;
    }
    // (4) zero parity-0 h fragments + prev fragments
    {
        uint4 z = make_uint4(0, 0, 0, 0);
        for (uint i = gtid; i < 5u * SEG_U4; i += gsz) {
            if (i < 4u * SEG_U4) g_hfrag[i] = z;
            else                 g_pfrag[i - 4u * SEG_U4] = z;
        }
    }
    gridbar();

    // ================= main autoregressive loop ==============================
    float creg0 = 0.f, hreg0 = 0.f, creg1 = 0.f, hreg1 = 0.f;
    const uint4* alo0 = g_awlo + (size_t)((0 + d) * 64 + ublk) * CHUNK_U4;
    const uint4* alo1 = g_awlo + (size_t)((2 + d) * 64 + ublk) * CHUNK_U4;

    for (int t = 0; t < 512; ++t) {
        const int pold = t & 1, pnew = pold ^ 1;

        // ---- layer 0 (cell = d): B = [x_t | prev | h_old] ----
        lstm_phase(sA, sR, alo0,
                   g_xfrag + (size_t)t * SEG_U4,
                   g_pfrag,
                   g_hfrag + (size_t)(pold * 4 + d) * SEG_U4,
                   bih + (size_t)d * 2048, bhh + (size_t)d * 2048,
                   creg0, hreg0,
                   g_hfrag + (size_t)(pnew * 4 + d) * SEG_U4, j0);
        gridbar();

        // ---- layer 1 (cell = 2+d): B = [h0_new | h1_new | h_old] ----
        lstm_phase(sA + 96 * 2 * 32, sR, alo1,
                   g_hfrag + (size_t)(pnew * 4 + 0) * SEG_U4,
                   g_hfrag + (size_t)(pnew * 4 + 1) * SEG_U4,
                   g_hfrag + (size_t)(pold * 4 + 2 + d) * SEG_U4,
                   bih + (size_t)(2 + d) * 2048, bhh + (size_t)(2 + d) * 2048,
                   creg1, hreg1,
                   g_hfrag + (size_t)(pnew * 4 + 2 + d) * SEG_U4, j0);
        gridbar();

        // ---- FC head on CTAs 0..31: 16 rows each; warps = npair(2) x kq(4) ----
        if (cta < 32) {
            if (wrp < 8) {
                const int npair = wrp & 1;
                const int kq    = wrp >> 1;        // 0..3, 16 ksteps each
                const uint4* A  = g_afcfrag + (size_t)cta * FCCHUNK_U4
                                  + (size_t)kq * 16 * 64 + lane;
                // kk global 0..63: seg = kk>>5 (h2 / h3), kin = kk&31
                Acc p0={0,0,0,0}, p1={0,0,0,0}, p2={0,0,0,0};
                Acc q0={0,0,0,0}, q1={0,0,0,0}, q2={0,0,0,0};
                #pragma unroll 4
                for (int k = 0; k < 16; ++k) {
                    int kk  = kq * 16 + k;
                    const uint4* B = g_hfrag
                        + (size_t)(pnew * 4 + 2 + (kk >> 5)) * SEG_U4
                        + (kk & 31) * 32 + npair * 2048 + lane;
                    uint4 v0 = B[0];
                    uint4 v1 = B[1024];
                    uint4 ah = __ldg(A + k * 64);
                    uint4 al = __ldg(A + k * 64 + 32);
                    mma_bf16(p0, ah, v0.x, v0.y);
                    mma_bf16(q0, ah, v1.x, v1.y);
                    mma_bf16(p1, ah, v0.z, v0.w);
                    mma_bf16(q1, ah, v1.z, v1.w);
                    mma_bf16(p2, al, v0.x, v0.y);
                    mma_bf16(q2, al, v1.x, v1.y);
                }
                const int gid = lane >> 2, tig = lane & 3;
                float* r = sR + kq * (16 * 33);
                // rows 0..15 (single mtile), cols npair*16 .. +16
                stacc(r, gid, npair * 16 + tig * 2,     p0, p1, p2);
                stacc(r, gid, npair * 16 + 8 + tig * 2, q0, q1, q2);
            }
            __syncthreads();
            if (tid < 256) {
                const int rr = tid >> 5, b = tid & 31;
                #pragma unroll
                for (int hh = 0; hh < 2; ++hh) {
                    int mr  = rr + hh * 8;
                    int row = cta * 16 + mr;
                    float v = __ldg(bfc + row);
                    #pragma unroll
                    for (int kq = 0; kq < 4; ++kq)
                        v += sR[kq * (16 * 33) + mr * 33 + b];
                    out[((size_t)b * 512 + t) * 512 + row] = v;
                    write_bfrag(g_pfrag, row, b, v);
                }
            }
        }
        gridbar();
    }

    // ================= epilogue: h_n, c_n from registers =====================
    if (tid < 256) {
        const size_t HN = 8388608ull;             // 32*512*512
        const size_t CN = HN + 65536ull;
        int ul = tid >> 5, b = tid & 31;
        int j = j0 + ul;
        out[HN + ((size_t)((0 + d) * 32 + b)) * 512 + j] = hreg0;
        out[HN + ((size_t)((2 + d) * 32 + b)) * 512 + j] = hreg1;
        out[CN + ((size_t)((0 + d) * 32 + b)) * 512 + j] = creg0;
        out[CN + ((size_t)((2 + d) * 32 + b)) * 512 + j] = creg1;
    }
}

extern "C" void kernel_launch(void* const* d_in, const int* in_sizes, int n_in,
                              void* d_out, int out_size) {
    (void)in_sizes; (void)n_in; (void)out_size;
    const float* x   = (const float*)d_in[0];
    const float* Wih = (const float*)d_in[2];
    const float* Whh = (const float*)d_in[3];
    const float* bih = (const float*)d_in[4];
    const float* bhh = (const float*)d_in[5];
    const float* Wfc = (const float*)d_in[6];
    const float* bfc = (const float*)d_in[7];
    cudaFuncSetAttribute(ar_encoder_mma4,
                         cudaFuncAttributeMaxDynamicSharedMemorySize, SMEM_BYTES);
    ar_encoder_mma4<<<NCTA, NTHR, SMEM_BYTES>>>(x, Wih, Whh, bih, bhh, Wfc, bfc,
                                                (float*)d_out);
}

// round 5
// speedup vs baseline: 2.6742x; 1.6618x over previous
#include <cuda_runtime.h>
#include <cuda_fp16.h>

typedef unsigned int uint;
typedef unsigned short ushort;

#define NTHR 384
#define NCTA 128

#define SEG_U2   4096u           // B segment: [4 ntile][32 kstep][32 lane] uint2 (fp16 pairs)
#define SA_U4    (2*96*2*32)     // A (weights) SMEM: [2 cell][96 kstep][2 mtile][32 lane] uint4
#define SR_FLOATS (6*32*33)
#define SMEM_BYTES (SA_U4*16 + SR_FLOATS*4)   // 196608 + 25344 = 221952

// Static device scratch (allocation-free)
__device__ uint2 g_xfrag[512u * SEG_U2];        // input x B-fragments, all t (~16MB)
__device__ uint2 g_hfrag[8u * SEG_U2];          // h fragments [parity][cell]
__device__ uint2 g_pfrag[SEG_U2];               // prev-pred fragments
__device__ uint4 g_afc[32u * 64u * 32u];        // FC A fragments [rowblk][kstep][lane] (1MB)
__device__ unsigned g_arrive = 0, g_release = 0;

// ---------------- grid barrier (monotonic ticket; 128 CTAs <= #SMs) ----------
__device__ __forceinline__ void gridbar() {
    __syncthreads();
    if (threadIdx.x == 0) {
        __threadfence();
        const unsigned nb = gridDim.x;
        unsigned ticket = atomicAdd(&g_arrive, 1u);
        if (ticket % nb == nb - 1u) {
            atomicAdd(&g_release, nb);
        } else {
            volatile unsigned* rel = &g_release;
            while ((int)(*rel - ticket) <= 0) __nanosleep(32);
        }
        __threadfence();
    }
    __syncthreads();
}

__device__ __forceinline__ float sigf(float v) { return 1.0f / (1.0f + expf(-v)); }

__device__ __forceinline__ uint pack2(float a, float b) {
    __half2 h = __floats2half2_rn(a, b);
    return *reinterpret_cast<uint*>(&h);
}

// Write one fp16 activation (k, n) into B-fragment layout.
__device__ __forceinline__ void write_hfrag(uint2* seg, int k, int n, float v) {
    ushort h = __half_as_ushort(__float2half_rn(v));
    int ks = k >> 4, kk = k & 15, nt = n >> 3;
    int tp  = ((n & 7) << 2) | ((kk >> 1) & 3);
    int reg = kk >> 3, hf = kk & 1;
    ushort* p = (ushort*)(seg + (size_t)(nt * 32 + ks) * 32 + tp);
    p[reg * 2 + hf] = h;
}

// ---------------- mma.sync m16n8k16 fp16 -> fp32 ------------------------------
struct Acc { float x, y, z, w; };

__device__ __forceinline__ void mma_f16(Acc& c, uint4 a, uint b0, uint b1) {
    asm volatile(
        "mma.sync.aligned.m16n8k16.row.col.f32.f16.f16.f32 "
        "{%0,%1,%2,%3}, {%4,%5,%6,%7}, {%8,%9}, {%0,%1,%2,%3};"
        : "+f"(c.x), "+f"(c.y), "+f"(c.z), "+f"(c.w)
        : "r"(a.x), "r"(a.y), "r"(a.z), "r"(a.w), "r"(b0), "r"(b1));
}

__device__ __forceinline__ void stacc1(float* r, int m0, int n0, Acc a) {
    r[m0 * 33 + n0]           = a.x;
    r[m0 * 33 + n0 + 1]       = a.y;
    r[(m0 + 8) * 33 + n0]     = a.z;
    r[(m0 + 8) * 33 + n0 + 1] = a.w;
}

// One LSTM phase. 12 warps: mtile = w&1, piece = w>>1 (16 ksteps each of 96).
// Warp covers all 4 ntiles (N=32) with 4 accumulators; A (SMEM) reused 4x.
__device__ __forceinline__ void lstm_phase(
    const uint4* __restrict__ sAc,     // SMEM A for this cell [96][2][32]
    float* sR,                          // [6][32][33]
    const uint2* __restrict__ B0,
    const uint2* __restrict__ B1,
    const uint2* __restrict__ B2,
    const float bias4[4],
    float& creg, float& hreg, uint2* hout, int j0)
{
    const int tid   = threadIdx.x;
    const int lane  = tid & 31;
    const int w     = tid >> 5;
    const int mtile = w & 1;
    const int piece = w >> 1;           // 0..5 (16 ksteps each)
    const int seg   = piece >> 1;

    const uint2* B  = (seg == 0 ? B0 : (seg == 1 ? B1 : B2))
                      + (piece & 1) * 16 * 32 + lane;
    const uint4* Ah = sAc + (piece * 32 + mtile) * 32 + lane;

    Acc c0={0,0,0,0}, c1={0,0,0,0}, c2={0,0,0,0}, c3={0,0,0,0};

    #pragma unroll
    for (int k = 0; k < 16; ++k) {
        uint2 v0 = __ldcg(B + k * 32);
        uint2 v1 = __ldcg(B + k * 32 + 1024);
        uint2 v2 = __ldcg(B + k * 32 + 2048);
        uint2 v3 = __ldcg(B + k * 32 + 3072);
        uint4 a  = Ah[k * 64];
        mma_f16(c0, a, v0.x, v0.y);
        mma_f16(c1, a, v1.x, v1.y);
        mma_f16(c2, a, v2.x, v2.y);
        mma_f16(c3, a, v3.x, v3.y);
    }

    const int gid = lane >> 2, tig = lane & 3;
    float* r = sR + piece * (32 * 33);
    const int m0 = mtile * 16 + gid;
    stacc1(r, m0, 0  + tig * 2, c0);
    stacc1(r, m0, 8  + tig * 2, c1);
    stacc1(r, m0, 16 + tig * 2, c2);
    stacc1(r, m0, 24 + tig * 2, c3);
    __syncthreads();

    if (tid < 256) {
        const int ul = tid >> 5, b = tid & 31;
        const int j  = j0 + ul;
        float g4[4];
        #pragma unroll
        for (int g = 0; g < 4; ++g) {
            int m = ul * 4 + g;
            float s = 0.f;
            #pragma unroll
            for (int p = 0; p < 6; ++p) s += sR[p * 1056 + m * 33 + b];
            g4[g] = s;
        }
        float gi = g4[0] + bias4[0];
        float gf = g4[1] + bias4[1];
        float gg = g4[2] + bias4[2];
        float go = g4[3] + bias4[3];
        float cc = sigf(gf) * creg + sigf(gi) * tanhf(gg);
        creg = cc;
        hreg = sigf(go) * tanhf(cc);
        write_hfrag(hout, j, b, hreg);
    }
}

// -----------------------------------------------------------------------------
extern "C" __global__ void __launch_bounds__(NTHR, 1)
ar_encoder_f16(const float* __restrict__ x,     // [32,512,512]
               const float* __restrict__ Wih,   // [4][2048][1024]
               const float* __restrict__ Whh,   // [4][2048][512]
               const float* __restrict__ bih,   // [4][2048]
               const float* __restrict__ bhh,   // [4][2048]
               const float* __restrict__ Wfc,   // [512][1024]
               const float* __restrict__ bfc,   // [512]
               float* __restrict__ out)
{
    extern __shared__ char smem[];
    uint4* sA = (uint4*)smem;                         // [2][96][2][32]
    float* sR = (float*)(smem + SA_U4 * 16);          // [6][32][33]

    const int tid  = threadIdx.x;
    const int cta  = blockIdx.x;
    const int lane = tid & 31;
    const int wrp  = tid >> 5;
    const int gsz  = NCTA * NTHR;
    const int gtid = cta * NTHR + tid;

    const int d    = cta >> 6;
    const int ublk = cta & 63;
    const int j0   = ublk * 8;

    // ================= prologue =============================================
    // (1) this CTA's LSTM weights -> SMEM fp16 A fragments
    for (int i = tid; i < 2 * 32 * 768; i += NTHR) {
        int kp = i % 768;
        int rm = i / 768;
        int m  = rm & 31;
        int ci = rm >> 5;
        int cell = ci ? (2 + d) : d;
        int row  = (m & 3) * 512 + j0 + (m >> 2);
        int k = kp * 2;
        float w0, w1;
        if (k < 1024) {
            const float* p = Wih + ((size_t)cell * 2048 + row) * 1024 + k;
            w0 = p[0]; w1 = p[1];
        } else {
            const float* p = Whh + ((size_t)cell * 2048 + row) * 512 + (k - 1024);
            w0 = p[0]; w1 = p[1];
        }
        uint packed = pack2(w0, w1);
        int kstep = k >> 4, kk = k & 15;
        int mtile = m >> 4, mrow = m & 15;
        int tp  = ((mrow & 7) << 2) | ((kk >> 1) & 3);
        int reg = (mrow >> 3) | ((kk >> 3) << 1);
        ((uint*)sA)[ ((((ci * 96 + kstep) * 2 + mtile) * 32) + tp) * 4 + reg ] = packed;
    }
    // (2) FC weights -> fp16 A fragments (grid-strided)
    for (uint i = gtid; i < 512u * 512u; i += gsz) {
        int kp = (int)(i & 511u), row = (int)(i >> 9);
        int k = kp * 2;
        const float* p = Wfc + ((size_t)row << 10) + k;
        uint packed = pack2(p[0], p[1]);
        int rowblk = row >> 4, mrow = row & 15;
        int kstep = k >> 4, kk = k & 15;
        int tp  = ((mrow & 7) << 2) | ((kk >> 1) & 3);
        int reg = (mrow >> 3) | ((kk >> 3) << 1);
        ((uint*)g_afc)[ (((rowblk * 64 + kstep) * 32) + tp) * 4 + reg ] = packed;
    }
    // (3) input x -> fp16 B fragments for all 512 steps
    for (uint s = gtid; s < 512u * SEG_U2; s += gsz) {
        int ln = (int)(s & 31), ks = (int)((s >> 5) & 31), nt = (int)((s >> 10) & 3);
        int t  = (int)(s >> 12);
        int tig = ln & 3, gid = ln >> 2;
        int n = nt * 8 + gid, k0 = ks * 16 + tig * 2;
        const float* xp = x + ((size_t)n * 512 + t) * 512 + k0;
        uint2 v;
        v.x = pack2(xp[0], xp[1]);
        v.y = pack2(xp[8], xp[9]);
        g_xfrag[s] = v;
    }
    // (4) zero h fragments (both parities) + prev fragments
    {
        uint2 z = make_uint2(0, 0);
        for (uint i = gtid; i < 9u * SEG_U2; i += gsz) {
            if (i < 8u * SEG_U2) g_hfrag[i] = z;
            else                 g_pfrag[i - 8u * SEG_U2] = z;
        }
    }

    // bias precompute (constant across steps)
    float bL0[4] = {0,0,0,0}, bL1[4] = {0,0,0,0};
    if (tid < 256) {
        int ul = tid >> 5, j = j0 + ul;
        #pragma unroll
        for (int g = 0; g < 4; ++g) {
            bL0[g] = __ldg(bih + (size_t)d * 2048 + g * 512 + j)
                   + __ldg(bhh + (size_t)d * 2048 + g * 512 + j);
            bL1[g] = __ldg(bih + (size_t)(2 + d) * 2048 + g * 512 + j)
                   + __ldg(bhh + (size_t)(2 + d) * 2048 + g * 512 + j);
        }
    }
    float bF[2] = {0, 0};
    if (cta < 32 && tid < 256) {
        int rr = tid >> 5;
        bF[0] = __ldg(bfc + cta * 16 + rr);
        bF[1] = __ldg(bfc + cta * 16 + rr + 8);
    }
    gridbar();

    // ================= main autoregressive loop ==============================
    float creg0 = 0.f, hreg0 = 0.f, creg1 = 0.f, hreg1 = 0.f;

    for (int t = 0; t < 512; ++t) {
        const int pold = t & 1, pnew = pold ^ 1;

        // ---- layer 0 (cell = d): B = [x_t | prev | h_old] ----
        lstm_phase(sA, sR,
                   g_xfrag + (size_t)t * SEG_U2,
                   g_pfrag,
                   g_hfrag + (size_t)(pold * 4 + d) * SEG_U2,
                   bL0, creg0, hreg0,
                   g_hfrag + (size_t)(pnew * 4 + d) * SEG_U2, j0);
        gridbar();

        // ---- layer 1 (cell = 2+d): B = [h0_new | h1_new | h_old] ----
        lstm_phase(sA + 96 * 2 * 32, sR,
                   g_hfrag + (size_t)(pnew * 4 + 0) * SEG_U2,
                   g_hfrag + (size_t)(pnew * 4 + 1) * SEG_U2,
                   g_hfrag + (size_t)(pold * 4 + 2 + d) * SEG_U2,
                   bL1, creg1, hreg1,
                   g_hfrag + (size_t)(pnew * 4 + 2 + d) * SEG_U2, j0);
        gridbar();

        // ---- FC head on CTAs 0..31: 16 rows each; 8 warps x 8 ksteps ----
        if (cta < 32) {
            if (wrp < 8) {
                const int kq = wrp;
                const uint4* A = g_afc + ((size_t)cta * 64 + kq * 8) * 32 + lane;
                const uint2* B = g_hfrag
                    + (size_t)(pnew * 4 + 2 + (kq >> 2)) * SEG_U2
                    + ((kq & 3) * 8) * 32 + lane;
                Acc c0={0,0,0,0}, c1={0,0,0,0}, c2={0,0,0,0}, c3={0,0,0,0};
                #pragma unroll
                for (int k = 0; k < 8; ++k) {
                    uint2 v0 = __ldcg(B + k * 32);
                    uint2 v1 = __ldcg(B + k * 32 + 1024);
                    uint2 v2 = __ldcg(B + k * 32 + 2048);
                    uint2 v3 = __ldcg(B + k * 32 + 3072);
                    uint4 a  = __ldg(A + k * 32);
                    mma_f16(c0, a, v0.x, v0.y);
                    mma_f16(c1, a, v1.x, v1.y);
                    mma_f16(c2, a, v2.x, v2.y);
                    mma_f16(c3, a, v3.x, v3.y);
                }
                const int gid = lane >> 2, tig = lane & 3;
                float* r = sR + kq * (16 * 33);
                stacc1(r, gid, 0  + tig * 2, c0);
                stacc1(r, gid, 8  + tig * 2, c1);
                stacc1(r, gid, 16 + tig * 2, c2);
                stacc1(r, gid, 24 + tig * 2, c3);
            }
            __syncthreads();
            if (tid < 256) {
                const int rr = tid >> 5, b = tid & 31;
                #pragma unroll
                for (int hh = 0; hh < 2; ++hh) {
                    int mr  = rr + hh * 8;
                    int row = cta * 16 + mr;
                    float v = bF[hh];
                    #pragma unroll
                    for (int kq = 0; kq < 8; ++kq)
                        v += sR[kq * 528 + mr * 33 + b];
                    out[((size_t)b * 512 + t) * 512 + row] = v;
                    write_hfrag(g_pfrag, row, b, v);
                }
            }
        }
        gridbar();
    }

    // ================= epilogue: h_n, c_n from registers =====================
    if (tid < 256) {
        const size_t HN = 8388608ull;             // 32*512*512
        const size_t CN = HN + 65536ull;
        int ul = tid >> 5, b = tid & 31;
        int j = j0 + ul;
        out[HN + ((size_t)((0 + d) * 32 + b)) * 512 + j] = hreg0;
        out[HN + ((size_t)((2 + d) * 32 + b)) * 512 + j] = hreg1;
        out[CN + ((size_t)((0 + d) * 32 + b)) * 512 + j] = creg0;
        out[CN + ((size_t)((2 + d) * 32 + b)) * 512 + j] = creg1;
    }
}

extern "C" void kernel_launch(void* const* d_in, const int* in_sizes, int n_in,
                              void* d_out, int out_size) {
    (void)in_sizes; (void)n_in; (void)out_size;
    const float* x   = (const float*)d_in[0];
    const float* Wih = (const float*)d_in[2];
    const float* Whh = (const float*)d_in[3];
    const float* bih = (const float*)d_in[4];
    const float* bhh = (const float*)d_in[5];
    const float* Wfc = (const float*)d_in[6];
    const float* bfc = (const float*)d_in[7];
    cudaFuncSetAttribute(ar_encoder_f16,
                         cudaFuncAttributeMaxDynamicSharedMemorySize, SMEM_BYTES);
    ar_encoder_f16<<<NCTA, NTHR, SMEM_BYTES>>>(x, Wih, Whh, bih, bhh, Wfc, bfc,
                                               (float*)d_out);
}

// round 6
// speedup vs baseline: 3.2339x; 1.2093x over previous
#include <cuda_runtime.h>
#include <cuda_fp16.h>

typedef unsigned int uint;
typedef unsigned short ushort;

#define NTHR 384
#define NCTA 128
#define SEG_U2 4096u            // B segment (K=512): [4 nt][32 ks][32 lane] uint2

#define SA0_U4 (64*2*32)        // L0 A smem: x(32ks)+h0(32ks), [ks][mtile][lane] uint4
#define SA1_U4 (96*2*32)        // L1 A smem
#define SR_OFF ((SA0_U4 + SA1_U4) * 16)      // 163840 B
#define SR_FLOATS (12*16*33)                 // 6336 floats (= 6*32*33)
#define SMEM_BYTES (SR_OFF + SR_FLOATS*4)    // 189184 B

// Static device scratch (allocation-free)
__device__ uint2 g_xfrag[512u * SEG_U2];          // x B-fragments per t   (~16MB)
__device__ uint2 g_h0frag[4u * SEG_U2];           // [parity][dir] layer0 h
__device__ uint2 g_h1hist[513ull * 2 * SEG_U2];   // h1cat history [t+1][seg] (~34MB)
__device__ uint4 g_Mfrag[128ull * 8192];          // M=Wp@Wfc frags, hi/lo  (~16MB)
__device__ uint4 g_afc[32u * 64u * 32u];          // FC A fragments (fp16)
__device__ uint2 g_wfcB[128u * 32u * 32u];        // Wfc B-frags for M build (1MB)
__device__ unsigned g_arrive = 0, g_release = 0;

// ---------------- grid barrier: acq_rel arrive + release/acquire flag --------
__device__ __forceinline__ void gridbar() {
    __syncthreads();
    if (threadIdx.x == 0) {
        const unsigned nb = gridDim.x;
        unsigned ticket;
        asm volatile("atom.add.acq_rel.gpu.u32 %0, [%1], %2;"
                     : "=r"(ticket) : "l"(&g_arrive), "r"(1u) : "memory");
        unsigned target = ticket - (ticket % nb) + nb;
        if (ticket % nb == nb - 1u) {
            asm volatile("red.add.release.gpu.u32 [%0], %1;"
                         :: "l"(&g_release), "r"(nb) : "memory");
        } else {
            unsigned rel;
            do {
                asm volatile("ld.acquire.gpu.u32 %0, [%1];"
                             : "=r"(rel) : "l"(&g_release) : "memory");
            } while ((int)(rel - target) < 0);
        }
    }
    __syncthreads();
}

__device__ __forceinline__ float sigf(float v) { return 1.0f / (1.0f + expf(-v)); }

__device__ __forceinline__ uint pack2(float a, float b) {
    __half2 h = __floats2half2_rn(a, b);
    return *reinterpret_cast<uint*>(&h);
}
__device__ __forceinline__ void split_f16(float a, float b, uint& hi, uint& lo) {
    __half ha = __float2half_rn(a), hb = __float2half_rn(b);
    float ra = a - __half2float(ha), rb = b - __half2float(hb);
    hi = (uint)__half_as_ushort(ha) | ((uint)__half_as_ushort(hb) << 16);
    lo = (uint)__half_as_ushort(__float2half_rn(ra))
       | ((uint)__half_as_ushort(__float2half_rn(rb)) << 16);
}

// Write one fp16 activation (k, n) into B-fragment layout.
__device__ __forceinline__ void write_hfrag(uint2* seg, int k, int n, float v) {
    ushort h = __half_as_ushort(__float2half_rn(v));
    int ks = k >> 4, kk = k & 15, nt = n >> 3;
    int tp  = ((n & 7) << 2) | ((kk >> 1) & 3);
    int reg = kk >> 3, hf = kk & 1;
    ushort* p = (ushort*)(seg + (size_t)(nt * 32 + ks) * 32 + tp);
    p[reg * 2 + hf] = h;
}

// ---------------- mma.sync m16n8k16 fp16 -> fp32 ------------------------------
struct Acc { float x, y, z, w; };

__device__ __forceinline__ void mma_f16(Acc& c, uint4 a, uint b0, uint b1) {
    asm volatile(
        "mma.sync.aligned.m16n8k16.row.col.f32.f16.f16.f32 "
        "{%0,%1,%2,%3}, {%4,%5,%6,%7}, {%8,%9}, {%0,%1,%2,%3};"
        : "+f"(c.x), "+f"(c.y), "+f"(c.z), "+f"(c.w)
        : "r"(a.x), "r"(a.y), "r"(a.z), "r"(a.w), "r"(b0), "r"(b1));
}

__device__ __forceinline__ void stacc1(float* r, int m0, int n0, Acc a) {
    r[m0 * 33 + n0]           = a.x;
    r[m0 * 33 + n0 + 1]       = a.y;
    r[(m0 + 8) * 33 + n0]     = a.z;
    r[(m0 + 8) * 33 + n0 + 1] = a.w;
}

// gate reduce + LSTM pointwise for first 256 threads
__device__ __forceinline__ void pointwise(const float* sR, const float* b4,
                                          float& creg, float& hreg,
                                          uint2* hout, int j0)
{
    const int tid = threadIdx.x;
    const int ul = tid >> 5, b = tid & 31;
    const int j = j0 + ul;
    float g4[4];
    #pragma unroll
    for (int g = 0; g < 4; ++g) {
        int m = ul * 4 + g;
        float s = b4[g];
        #pragma unroll
        for (int p = 0; p < 6; ++p) s += sR[p * 1056 + m * 33 + b];
        g4[g] = s;
    }
    float cc = sigf(g4[1]) * creg + sigf(g4[0]) * tanhf(g4[2]);
    creg = cc;
    hreg = sigf(g4[3]) * tanhf(cc);
    write_hfrag(hout, j, b, hreg);
}

// -----------------------------------------------------------------------------
extern "C" __global__ void __launch_bounds__(NTHR, 1)
ar_encoder_v6(const float* __restrict__ x,     // [32,512,512]
              const float* __restrict__ Wih,   // [4][2048][1024]
              const float* __restrict__ Whh,   // [4][2048][512]
              const float* __restrict__ bih,   // [4][2048]
              const float* __restrict__ bhh,   // [4][2048]
              const float* __restrict__ Wfc,   // [512][1024]
              const float* __restrict__ bfc,   // [512]
              float* __restrict__ out)
{
    extern __shared__ char smem[];
    uint4* sA0 = (uint4*)smem;                       // [64 ks][2 mt][32 ln]
    uint4* sA1 = sA0 + SA0_U4;                       // [96 ks][2 mt][32 ln]
    float* sR  = (float*)(smem + SR_OFF);            // 6336 floats

    const int tid  = threadIdx.x;
    const int cta  = blockIdx.x;
    const int lane = tid & 31;
    const int wrp  = tid >> 5;
    const int gsz  = NCTA * NTHR;
    const int gtid = cta * NTHR + tid;

    const int d    = cta >> 6;
    const int ublk = cta & 63;
    const int j0   = ublk * 8;
    const size_t ctaM = (size_t)cta * 8192;          // uint4 units into g_Mfrag

    // ================= prologue phase 1 =====================================
    // (a) L0 weights (Wx + Wh0) -> sA0
    for (int i = tid; i < 32 * 512; i += NTHR) {
        int kp = i & 511, m = i >> 9;
        int grow = (m & 3) * 512 + j0 + (m >> 2);
        int k, ks; const float* p;
        if (kp < 256) { k = kp * 2; ks = k >> 4;
                        p = Wih + ((size_t)d * 2048 + grow) * 1024 + k; }
        else          { k = (kp - 256) * 2; ks = 32 + (k >> 4);
                        p = Whh + ((size_t)d * 2048 + grow) * 512 + k; }
        uint packed = pack2(p[0], p[1]);
        int kk = k & 15, mtile = m >> 4, mrow = m & 15;
        int tp  = ((mrow & 7) << 2) | ((kk >> 1) & 3);
        int reg = (mrow >> 3) | ((kk >> 3) << 1);
        ((uint*)sA0)[((ks * 2 + mtile) * 32 + tp) * 4 + reg] = packed;
    }
    // (b) Wp (prev-columns of Wih layer0) -> sA1 as TEMP A-fragments (K=512)
    for (int i = tid; i < 32 * 256; i += NTHR) {
        int kp = i & 255, m = i >> 8;
        int grow = (m & 3) * 512 + j0 + (m >> 2);
        int k = kp * 2;
        const float* p = Wih + ((size_t)d * 2048 + grow) * 1024 + 512 + k;
        uint packed = pack2(p[0], p[1]);
        int ks = k >> 4, kk = k & 15, mtile = m >> 4, mrow = m & 15;
        int tp  = ((mrow & 7) << 2) | ((kk >> 1) & 3);
        int reg = (mrow >> 3) | ((kk >> 3) << 1);
        ((uint*)sA1)[((ks * 2 + mtile) * 32 + tp) * 4 + reg] = packed;
    }
    // (c) Wfc -> B-fragments for the M GEMM (grid-strided)
    for (uint i = gtid; i < 128u * 32u * 32u; i += gsz) {
        int ln = (int)(i & 31), ks = (int)((i >> 5) & 31), nt = (int)(i >> 10);
        int n  = nt * 8 + (ln >> 2);
        int o0 = ks * 16 + (ln & 3) * 2;
        uint2 v;
        v.x = pack2(Wfc[(size_t)o0 * 1024 + n],       Wfc[(size_t)(o0 + 1) * 1024 + n]);
        v.y = pack2(Wfc[(size_t)(o0 + 8) * 1024 + n], Wfc[(size_t)(o0 + 9) * 1024 + n]);
        g_wfcB[i] = v;
    }
    // (d) FC weights -> fp16 A fragments
    for (uint i = gtid; i < 512u * 512u; i += gsz) {
        int kp = (int)(i & 511u), row = (int)(i >> 9);
        int k = kp * 2;
        const float* p = Wfc + ((size_t)row << 10) + k;
        uint packed = pack2(p[0], p[1]);
        int rowblk = row >> 4, mrow = row & 15;
        int kstep = k >> 4, kk = k & 15;
        int tp  = ((mrow & 7) << 2) | ((kk >> 1) & 3);
        int reg = (mrow >> 3) | ((kk >> 3) << 1);
        ((uint*)g_afc)[(((rowblk * 64 + kstep) * 32) + tp) * 4 + reg] = packed;
    }
    // (e) input x -> fp16 B fragments, all t
    for (uint s = gtid; s < 512u * SEG_U2; s += gsz) {
        int ln = (int)(s & 31), ks = (int)((s >> 5) & 31), nt = (int)((s >> 10) & 3);
        int t  = (int)(s >> 12);
        int tig = ln & 3, gid = ln >> 2;
        int n = nt * 8 + gid, k0 = ks * 16 + tig * 2;
        const float* xp = x + ((size_t)n * 512 + t) * 512 + k0;
        uint2 v;
        v.x = pack2(xp[0], xp[1]);
        v.y = pack2(xp[8], xp[9]);
        g_xfrag[s] = v;
    }
    // (f) zero h0frag (both parities) + hist[0]
    {
        uint2 z = make_uint2(0, 0);
        for (uint i = gtid; i < 6u * SEG_U2; i += gsz) {
            if (i < 4u * SEG_U2) g_h0frag[i] = z;
            else                 g_h1hist[i - 4u * SEG_U2] = z;
        }
    }
    gridbar();   // wfcB ready everywhere

    // ================= prologue phase 2: M = Wp @ Wfc (fp16 MMA) =============
    {
        const int mtile = wrp & 1;
        for (int nt = (wrp >> 1); nt < 128; nt += 6) {
            Acc c = {0, 0, 0, 0};
            const uint2* B = g_wfcB + (size_t)nt * 1024 + lane;
            const uint4* A = sA1 + mtile * 32 + lane;
            #pragma unroll 8
            for (int ks = 0; ks < 32; ++ks) {
                uint2 v = __ldcg(B + ks * 32);
                uint4 a = A[ks * 64];
                mma_f16(c, a, v.x, v.y);
            }
            int gid = lane >> 2, tig = lane & 3;
            int h = nt * 8 + tig * 2, kk = h & 15, kstep = h >> 4;
            int tp = ((gid & 7) << 2) | ((kk >> 1) & 3);
            uint hi0, lo0, hi1, lo1;
            split_f16(c.x, c.y, hi0, lo0);   // mrow = gid
            split_f16(c.z, c.w, hi1, lo1);   // mrow = gid + 8
            size_t bhi = ctaM + (size_t)((kstep * 2 + mtile) * 2) * 32 + tp;
            size_t blo = bhi + 32;
            int rhib = (kk >> 3) << 1;
            ((uint*)g_Mfrag)[bhi * 4 + rhib]     = hi0;
            ((uint*)g_Mfrag)[bhi * 4 + 1 + rhib] = hi1;
            ((uint*)g_Mfrag)[blo * 4 + rhib]     = lo0;
            ((uint*)g_Mfrag)[blo * 4 + 1 + rhib] = lo1;
        }
    }
    __syncthreads();

    // (g) now fill sA1 with the real L1 weights (K=1536)
    for (int i = tid; i < 32 * 768; i += NTHR) {
        int kp = i % 768, m = i / 768;
        int grow = (m & 3) * 512 + j0 + (m >> 2);
        int k = kp * 2; const float* p;
        if (k < 1024) p = Wih + ((size_t)(2 + d) * 2048 + grow) * 1024 + k;
        else          p = Whh + ((size_t)(2 + d) * 2048 + grow) * 512 + (k - 1024);
        uint packed = pack2(p[0], p[1]);
        int ks = k >> 4, kk = k & 15, mtile = m >> 4, mrow = m & 15;
        int tp  = ((mrow & 7) << 2) | ((kk >> 1) & 3);
        int reg = (mrow >> 3) | ((kk >> 3) << 1);
        ((uint*)sA1)[((ks * 2 + mtile) * 32 + tp) * 4 + reg] = packed;
    }

    // (h) biases: bA0 (t=0), bB0 (t>=1, += Wp@bfc), bA1
    float bA0[4] = {0,0,0,0}, bB0[4] = {0,0,0,0}, bA1[4] = {0,0,0,0};
    if (tid < 256) {
        int ul = tid >> 5, j = j0 + ul;
        #pragma unroll
        for (int g = 0; g < 4; ++g) {
            bA0[g] = __ldg(bih + (size_t)d * 2048 + g * 512 + j)
                   + __ldg(bhh + (size_t)d * 2048 + g * 512 + j);
            bA1[g] = __ldg(bih + (size_t)(2 + d) * 2048 + g * 512 + j)
                   + __ldg(bhh + (size_t)(2 + d) * 2048 + g * 512 + j);
            int grow = g * 512 + j;
            const float* wp = Wih + ((size_t)d * 2048 + grow) * 1024 + 512;
            float p = 0.f;
            for (int o = lane; o < 512; o += 32) p += wp[o] * __ldg(bfc + o);
            #pragma unroll
            for (int s = 16; s; s >>= 1) p += __shfl_xor_sync(0xffffffffu, p, s);
            bB0[g] = bA0[g] + p;
        }
    }
    gridbar();

    // ================= main autoregressive loop ==============================
    float creg0 = 0.f, hreg0 = 0.f, creg1 = 0.f, hreg1 = 0.f;
    const int mtile = wrp & 1;
    const int piece = wrp >> 1;

    for (int t = 0; t < 512; ++t) {
        const int pold = t & 1, pnew = pold ^ 1;
        const uint2* histT = g_h1hist + (size_t)t * 2 * SEG_U2;

        // ---- L0: gates = Wx@x + M@h1cat(t-1) + Wh0@h0(t-1) ----
        {
            Acc c0={0,0,0,0}, c1={0,0,0,0}, c2={0,0,0,0}, c3={0,0,0,0};
            if (piece == 0 || piece == 5) {
                const uint4* A = sA0 + ((piece == 0 ? 0 : 64) + mtile) * 32 + lane;
                const uint2* B = (piece == 0)
                    ? g_xfrag + (size_t)t * SEG_U2 + lane
                    : g_h0frag + (size_t)(pold * 2 + d) * SEG_U2 + lane;
                #pragma unroll 8
                for (int k = 0; k < 32; ++k) {
                    uint2 v0 = __ldcg(B + k * 32);
                    uint2 v1 = __ldcg(B + k * 32 + 1024);
                    uint2 v2 = __ldcg(B + k * 32 + 2048);
                    uint2 v3 = __ldcg(B + k * 32 + 3072);
                    uint4 a  = A[k * 64];
                    mma_f16(c0, a, v0.x, v0.y);
                    mma_f16(c1, a, v1.x, v1.y);
                    mma_f16(c2, a, v2.x, v2.y);
                    mma_f16(c3, a, v3.x, v3.y);
                }
            } else {
                const int km0 = (piece - 1) * 16;
                const uint4* A = g_Mfrag + ctaM
                    + (size_t)((km0 * 2 + mtile) * 2) * 32 + lane;
                const uint2* B = histT + (size_t)(km0 >> 5) * SEG_U2
                    + (km0 & 31) * 32 + lane;
                #pragma unroll 4
                for (int k = 0; k < 16; ++k) {
                    uint2 v0 = __ldcg(B + k * 32);
                    uint2 v1 = __ldcg(B + k * 32 + 1024);
                    uint2 v2 = __ldcg(B + k * 32 + 2048);
                    uint2 v3 = __ldcg(B + k * 32 + 3072);
                    uint4 ah = __ldg(A + k * 128);
                    uint4 al = __ldg(A + k * 128 + 32);
                    mma_f16(c0, ah, v0.x, v0.y);
                    mma_f16(c1, ah, v1.x, v1.y);
                    mma_f16(c2, ah, v2.x, v2.y);
                    mma_f16(c3, ah, v3.x, v3.y);
                    mma_f16(c0, al, v0.x, v0.y);
                    mma_f16(c1, al, v1.x, v1.y);
                    mma_f16(c2, al, v2.x, v2.y);
                    mma_f16(c3, al, v3.x, v3.y);
                }
            }
            const int gid = lane >> 2, tig = lane & 3;
            float* r = sR + piece * 1056;
            const int m0 = mtile * 16 + gid;
            stacc1(r, m0, 0  + tig * 2, c0);
            stacc1(r, m0, 8  + tig * 2, c1);
            stacc1(r, m0, 16 + tig * 2, c2);
            stacc1(r, m0, 24 + tig * 2, c3);
            __syncthreads();
            if (tid < 256)
                pointwise(sR, t == 0 ? bA0 : bB0, creg0, hreg0,
                          g_h0frag + (size_t)(pnew * 2 + d) * SEG_U2, j0);
        }
        gridbar();

        // ---- L1: gates = W@[h0f|h0b] + Whh@h1(t-1) ----
        {
            const int seg = piece >> 1, off16 = (piece & 1) * 16;
            const uint2* Bb =
                (seg == 0) ? g_h0frag + (size_t)(pnew * 2 + 0) * SEG_U2 :
                (seg == 1) ? g_h0frag + (size_t)(pnew * 2 + 1) * SEG_U2 :
                             histT + (size_t)d * SEG_U2;
            const uint2* B = Bb + off16 * 32 + lane;
            const uint4* A = sA1 + ((piece * 16) * 2 + mtile) * 32 + lane;
            Acc c0={0,0,0,0}, c1={0,0,0,0}, c2={0,0,0,0}, c3={0,0,0,0};
            #pragma unroll 8
            for (int k = 0; k < 16; ++k) {
                uint2 v0 = __ldcg(B + k * 32);
                uint2 v1 = __ldcg(B + k * 32 + 1024);
                uint2 v2 = __ldcg(B + k * 32 + 2048);
                uint2 v3 = __ldcg(B + k * 32 + 3072);
                uint4 a  = A[k * 64];
                mma_f16(c0, a, v0.x, v0.y);
                mma_f16(c1, a, v1.x, v1.y);
                mma_f16(c2, a, v2.x, v2.y);
                mma_f16(c3, a, v3.x, v3.y);
            }
            const int gid = lane >> 2, tig = lane & 3;
            float* r = sR + piece * 1056;
            const int m0 = mtile * 16 + gid;
            stacc1(r, m0, 0  + tig * 2, c0);
            stacc1(r, m0, 8  + tig * 2, c1);
            stacc1(r, m0, 16 + tig * 2, c2);
            stacc1(r, m0, 24 + tig * 2, c3);
            __syncthreads();
            if (tid < 256)
                pointwise(sR, bA1, creg1, hreg1,
                          g_h1hist + ((size_t)(t + 1) * 2 + d) * SEG_U2, j0);
        }
        gridbar();
    }

    // ================= batched FC over all t =================================
    // outputs[b][t][:] = Wfc @ h1cat(t) + bfc, h1cat(t) = hist[t+1]
    {
        float* sRw = sR + wrp * 528;                 // [16][33] per warp
        for (int tt = 0; tt < 4; ++tt) {
            const int t = cta + tt * 128;
            const uint2* Bbase = g_h1hist + (size_t)(t + 1) * 2 * SEG_U2;
            for (int rb = wrp; rb < 32; rb += 12) {
                const uint4* A = g_afc + (size_t)(rb * 64) * 32 + lane;
                Acc c0={0,0,0,0}, c1={0,0,0,0}, c2={0,0,0,0}, c3={0,0,0,0};
                #pragma unroll 4
                for (int ks = 0; ks < 64; ++ks) {
                    const uint2* B = Bbase + (size_t)(ks >> 5) * SEG_U2
                                   + (ks & 31) * 32 + lane;
                    uint2 v0 = __ldcg(B);
                    uint2 v1 = __ldcg(B + 1024);
                    uint2 v2 = __ldcg(B + 2048);
                    uint2 v3 = __ldcg(B + 3072);
                    uint4 a  = __ldg(A + ks * 32);
                    mma_f16(c0, a, v0.x, v0.y);
                    mma_f16(c1, a, v1.x, v1.y);
                    mma_f16(c2, a, v2.x, v2.y);
                    mma_f16(c3, a, v3.x, v3.y);
                }
                const int gid = lane >> 2, tig = lane & 3;
                stacc1(sRw, gid, 0  + tig * 2, c0);
                stacc1(sRw, gid, 8  + tig * 2, c1);
                stacc1(sRw, gid, 16 + tig * 2, c2);
                stacc1(sRw, gid, 24 + tig * 2, c3);
                __syncwarp();
                // coalesced-ish store: lane = batch b, 16 consecutive rows
                float* op = out + ((size_t)lane * 512 + t) * 512 + rb * 16;
                #pragma unroll
                for (int q = 0; q < 4; ++q) {
                    float v0 = sRw[(q*4+0) * 33 + lane] + __ldg(bfc + rb*16 + q*4+0);
                    float v1 = sRw[(q*4+1) * 33 + lane] + __ldg(bfc + rb*16 + q*4+1);
                    float v2 = sRw[(q*4+2) * 33 + lane] + __ldg(bfc + rb*16 + q*4+2);
                    float v3 = sRw[(q*4+3) * 33 + lane] + __ldg(bfc + rb*16 + q*4+3);
                    *(float4*)(op + q * 4) = make_float4(v0, v1, v2, v3);
                }
                __syncwarp();
            }
        }
    }

    // ================= epilogue: h_n, c_n from registers =====================
    if (tid < 256) {
        const size_t HN = 8388608ull;             // 32*512*512
        const size_t CN = HN + 65536ull;
        int ul = tid >> 5, b = tid & 31;
        int j = j0 + ul;
        out[HN + ((size_t)((0 + d) * 32 + b)) * 512 + j] = hreg0;
        out[HN + ((size_t)((2 + d) * 32 + b)) * 512 + j] = hreg1;
        out[CN + ((size_t)((0 + d) * 32 + b)) * 512 + j] = creg0;
        out[CN + ((size_t)((2 + d) * 32 + b)) * 512 + j] = creg1;
    }
}

extern "C" void kernel_launch(void* const* d_in, const int* in_sizes, int n_in,
                              void* d_out, int out_size) {
    (void)in_sizes; (void)n_in; (void)out_size;
    const float* x   = (const float*)d_in[0];
    const float* Wih = (const float*)d_in[2];
    const float* Whh = (const float*)d_in[3];
    const float* bih = (const float*)d_in[4];
    const float* bhh = (const float*)d_in[5];
    const float* Wfc = (const float*)d_in[6];
    const float* bfc = (const float*)d_in[7];
    cudaFuncSetAttribute(ar_encoder_v6,
                         cudaFuncAttributeMaxDynamicSharedMemorySize, SMEM_BYTES);
    ar_encoder_v6<<<NCTA, NTHR, SMEM_BYTES>>>(x, Wih, Whh, bih, bhh, Wfc, bfc,
                                              (float*)d_out);
}

// round 7
// speedup vs baseline: 3.2481x; 1.0044x over previous
#include <cuda_runtime.h>
#include <cuda_fp16.h>

typedef unsigned int uint;
typedef unsigned short ushort;

#define NTHR 384
#define NCTA 128
#define SEG_U2 4096u            // B segment (K=512): [4 nt][32 ks][32 lane] uint2

// SMEM layout (bytes)
#define SA0_OFF 0               // L0 x+h0 weights [64 ks][2 mt][32 ln] uint4 = 65536
#define SA1_OFF 65536           // L1 h0f+h0b weights [64 ks][2 mt][32 ln]   = 65536
#define SM_OFF  131072          // M-hi fragments [64 ks][2 mt][32 ln]       = 65536
#define SR_OFF  196608          // reduce buffer 6336 floats                 = 25344
#define SMEM_BYTES (196608 + 25344)

// Static device scratch (allocation-free)
__device__ uint2 g_xfrag[512u * SEG_U2];          // x B-fragments per t (~16MB)
__device__ uint2 g_h0frag[4u * SEG_U2];           // [parity][dir] layer0 h
__device__ uint2 g_h1hist[513ull * 2 * SEG_U2];   // h1cat history [t+1][dir] (~34MB)
__device__ uint4 g_Mlo[128ull * 4096];            // per-CTA M-lo fragments (8MB)
__device__ uint4 g_w1h[128ull * 2048];            // per-CTA L1 Whh fragments (4MB)
__device__ uint4 g_afc[32u * 64u * 32u];          // FC A fragments (fp16)
__device__ uint2 g_wfcB[128u * 32u * 32u];        // Wfc B-frags for M build
__device__ unsigned g_arrive = 0, g_release = 0;  // prologue/epilogue barrier
__device__ unsigned g_cnt0 = 0, g_cnt1 = 0;       // dataflow epoch counters

// ---------------- grid barrier (prologue/epilogue only) ----------------------
__device__ __forceinline__ void gridbar() {
    __syncthreads();
    if (threadIdx.x == 0) {
        const unsigned nb = gridDim.x;
        unsigned ticket;
        asm volatile("atom.add.acq_rel.gpu.u32 %0, [%1], %2;"
                     : "=r"(ticket) : "l"(&g_arrive), "r"(1u) : "memory");
        unsigned target = ticket - (ticket % nb) + nb;
        if (ticket % nb == nb - 1u) {
            asm volatile("red.add.release.gpu.u32 [%0], %1;"
                         :: "l"(&g_release), "r"(nb) : "memory");
        } else {
            unsigned rel;
            do {
                asm volatile("ld.acquire.gpu.u32 %0, [%1];"
                             : "=r"(rel) : "l"(&g_release) : "memory");
            } while ((int)(rel - target) < 0);
        }
    }
    __syncthreads();
}

// per-warp dataflow wait: lane0 acquires counter, warp joins
__device__ __forceinline__ void warp_wait(unsigned* cnt, unsigned tgt) {
    if ((threadIdx.x & 31) == 0) {
        unsigned v;
        do {
            asm volatile("ld.acquire.gpu.u32 %0, [%1];"
                         : "=r"(v) : "l"(cnt) : "memory");
        } while ((int)(v - tgt) < 0);
    }
    __syncwarp();
}

// CTA publish: all writers fence, then one release-increment
__device__ __forceinline__ void publish(unsigned* cnt) {
    __threadfence();
    __syncthreads();
    if (threadIdx.x == 0)
        asm volatile("red.add.release.gpu.u32 [%0], %1;"
                     :: "l"(cnt), "r"(1u) : "memory");
}

// ---------------- fast activations -------------------------------------------
__device__ __forceinline__ float sigf(float v) {
    return __fdividef(1.f, 1.f + __expf(-v));
}
__device__ __forceinline__ float tanhf_fast(float v) {
    float vc = fminf(fmaxf(v, -15.f), 15.f);
    float e  = __expf(-2.f * vc);
    return __fdividef(1.f - e, 1.f + e);
}

__device__ __forceinline__ uint pack2(float a, float b) {
    __half2 h = __floats2half2_rn(a, b);
    return *reinterpret_cast<uint*>(&h);
}
__device__ __forceinline__ void split_f16(float a, float b, uint& hi, uint& lo) {
    __half ha = __float2half_rn(a), hb = __float2half_rn(b);
    float ra = a - __half2float(ha), rb = b - __half2float(hb);
    hi = (uint)__half_as_ushort(ha) | ((uint)__half_as_ushort(hb) << 16);
    lo = (uint)__half_as_ushort(__float2half_rn(ra))
       | ((uint)__half_as_ushort(__float2half_rn(rb)) << 16);
}

// Write one fp16 activation (k, n) into B-fragment layout.
__device__ __forceinline__ void write_hfrag(uint2* seg, int k, int n, float v) {
    ushort h = __half_as_ushort(__float2half_rn(v));
    int ks = k >> 4, kk = k & 15, nt = n >> 3;
    int tp  = ((n & 7) << 2) | ((kk >> 1) & 3);
    int reg = kk >> 3, hf = kk & 1;
    ushort* p = (ushort*)(seg + (size_t)(nt * 32 + ks) * 32 + tp);
    p[reg * 2 + hf] = h;
}

// ---------------- mma.sync m16n8k16 fp16 -> fp32 ------------------------------
struct Acc { float x, y, z, w; };

__device__ __forceinline__ void mma_f16(Acc& c, uint4 a, uint b0, uint b1) {
    asm volatile(
        "mma.sync.aligned.m16n8k16.row.col.f32.f16.f16.f32 "
        "{%0,%1,%2,%3}, {%4,%5,%6,%7}, {%8,%9}, {%0,%1,%2,%3};"
        : "+f"(c.x), "+f"(c.y), "+f"(c.z), "+f"(c.w)
        : "r"(a.x), "r"(a.y), "r"(a.z), "r"(a.w), "r"(b0), "r"(b1));
}

__device__ __forceinline__ void stacc1(float* r, int m0, int n0, Acc a) {
    r[m0 * 33 + n0]           = a.x;
    r[m0 * 33 + n0 + 1]       = a.y;
    r[(m0 + 8) * 33 + n0]     = a.z;
    r[(m0 + 8) * 33 + n0 + 1] = a.w;
}

// gate reduce + LSTM pointwise for first 256 threads
__device__ __forceinline__ void pointwise(const float* sR, const float* b4,
                                          float& creg, float& hreg,
                                          uint2* hout, int j0)
{
    const int tid = threadIdx.x;
    const int ul = tid >> 5, b = tid & 31;
    const int j = j0 + ul;
    float g4[4];
    #pragma unroll
    for (int g = 0; g < 4; ++g) {
        int m = ul * 4 + g;
        float s = b4[g];
        #pragma unroll
        for (int p = 0; p < 6; ++p) s += sR[p * 1056 + m * 33 + b];
        g4[g] = s;
    }
    float cc = sigf(g4[1]) * creg + sigf(g4[0]) * tanhf_fast(g4[2]);
    creg = cc;
    hreg = sigf(g4[3]) * tanhf_fast(cc);
    write_hfrag(hout, j, b, hreg);
}

// -----------------------------------------------------------------------------
extern "C" __global__ void __launch_bounds__(NTHR, 1)
ar_encoder_v7(const float* __restrict__ x,     // [32,512,512]
              const float* __restrict__ Wih,   // [4][2048][1024]
              const float* __restrict__ Whh,   // [4][2048][512]
              const float* __restrict__ bih,   // [4][2048]
              const float* __restrict__ bhh,   // [4][2048]
              const float* __restrict__ Wfc,   // [512][1024]
              const float* __restrict__ bfc,   // [512]
              float* __restrict__ out)
{
    extern __shared__ char smem[];
    uint4* sA0 = (uint4*)(smem + SA0_OFF);
    uint4* sA1 = (uint4*)(smem + SA1_OFF);
    uint4* sM  = (uint4*)(smem + SM_OFF);
    float* sR  = (float*)(smem + SR_OFF);

    const int tid  = threadIdx.x;
    const int cta  = blockIdx.x;
    const int lane = tid & 31;
    const int wrp  = tid >> 5;
    const int gsz  = NCTA * NTHR;
    const int gtid = cta * NTHR + tid;

    const int d    = cta >> 6;
    const int ublk = cta & 63;
    const int j0   = ublk * 8;

    // ================= prologue phase 1 =====================================
    // (a) L0 weights (Wx + Wh0) -> sA0
    for (int i = tid; i < 32 * 512; i += NTHR) {
        int kp = i & 511, m = i >> 9;
        int grow = (m & 3) * 512 + j0 + (m >> 2);
        int k, ks; const float* p;
        if (kp < 256) { k = kp * 2; ks = k >> 4;
                        p = Wih + ((size_t)d * 2048 + grow) * 1024 + k; }
        else          { k = (kp - 256) * 2; ks = 32 + (k >> 4);
                        p = Whh + ((size_t)d * 2048 + grow) * 512 + k; }
        uint packed = pack2(p[0], p[1]);
        int kk = k & 15, mtile = m >> 4, mrow = m & 15;
        int tp  = ((mrow & 7) << 2) | ((kk >> 1) & 3);
        int reg = (mrow >> 3) | ((kk >> 3) << 1);
        ((uint*)sA0)[((ks * 2 + mtile) * 32 + tp) * 4 + reg] = packed;
    }
    // (b) Wp (prev-columns of Wih layer0) -> sA1 as TEMP A-fragments (K=512)
    for (int i = tid; i < 32 * 256; i += NTHR) {
        int kp = i & 255, m = i >> 8;
        int grow = (m & 3) * 512 + j0 + (m >> 2);
        int k = kp * 2;
        const float* p = Wih + ((size_t)d * 2048 + grow) * 1024 + 512 + k;
        uint packed = pack2(p[0], p[1]);
        int ks = k >> 4, kk = k & 15, mtile = m >> 4, mrow = m & 15;
        int tp  = ((mrow & 7) << 2) | ((kk >> 1) & 3);
        int reg = (mrow >> 3) | ((kk >> 3) << 1);
        ((uint*)sA1)[((ks * 2 + mtile) * 32 + tp) * 4 + reg] = packed;
    }
    // (c) Wfc -> B-fragments for the M GEMM (grid-strided)
    for (uint i = gtid; i < 128u * 32u * 32u; i += gsz) {
        int ln = (int)(i & 31), ks = (int)((i >> 5) & 31), nt = (int)(i >> 10);
        int n  = nt * 8 + (ln >> 2);
        int o0 = ks * 16 + (ln & 3) * 2;
        uint2 v;
        v.x = pack2(Wfc[(size_t)o0 * 1024 + n],       Wfc[(size_t)(o0 + 1) * 1024 + n]);
        v.y = pack2(Wfc[(size_t)(o0 + 8) * 1024 + n], Wfc[(size_t)(o0 + 9) * 1024 + n]);
        g_wfcB[i] = v;
    }
    // (d) FC weights -> fp16 A fragments
    for (uint i = gtid; i < 512u * 512u; i += gsz) {
        int kp = (int)(i & 511u), row = (int)(i >> 9);
        int k = kp * 2;
        const float* p = Wfc + ((size_t)row << 10) + k;
        uint packed = pack2(p[0], p[1]);
        int rowblk = row >> 4, mrow = row & 15;
        int kstep = k >> 4, kk = k & 15;
        int tp  = ((mrow & 7) << 2) | ((kk >> 1) & 3);
        int reg = (mrow >> 3) | ((kk >> 3) << 1);
        ((uint*)g_afc)[(((rowblk * 64 + kstep) * 32) + tp) * 4 + reg] = packed;
    }
    // (e) input x -> fp16 B fragments, all t
    for (uint s = gtid; s < 512u * SEG_U2; s += gsz) {
        int ln = (int)(s & 31), ks = (int)((s >> 5) & 31), nt = (int)((s >> 10) & 3);
        int t  = (int)(s >> 12);
        int tig = ln & 3, gid = ln >> 2;
        int n = nt * 8 + gid, k0 = ks * 16 + tig * 2;
        const float* xp = x + ((size_t)n * 512 + t) * 512 + k0;
        uint2 v;
        v.x = pack2(xp[0], xp[1]);
        v.y = pack2(xp[8], xp[9]);
        g_xfrag[s] = v;
    }
    // (f) zero h0frag (both parities) + hist[0]
    {
        uint2 z = make_uint2(0, 0);
        for (uint i = gtid; i < 6u * SEG_U2; i += gsz) {
            if (i < 4u * SEG_U2) g_h0frag[i] = z;
            else                 g_h1hist[i - 4u * SEG_U2] = z;
        }
    }
    gridbar();   // wfcB / xfrag / zeros / afc visible everywhere

    // ================= prologue phase 2: M = Wp @ Wfc ========================
    // hi -> sM (SMEM, persistent), lo -> g_Mlo[cta]
    {
        const int mtile = wrp & 1;
        uint* mhi = (uint*)sM;
        uint* mlo = (uint*)(g_Mlo + (size_t)cta * 4096);
        for (int nt = (wrp >> 1); nt < 128; nt += 6) {
            Acc c = {0, 0, 0, 0};
            const uint2* B = g_wfcB + (size_t)nt * 1024 + lane;
            const uint4* A = sA1 + mtile * 32 + lane;
            #pragma unroll 8
            for (int ks = 0; ks < 32; ++ks) {
                uint2 v = __ldcg(B + ks * 32);
                uint4 a = A[ks * 64];
                mma_f16(c, a, v.x, v.y);
            }
            int gid = lane >> 2, tig = lane & 3;
            int h = nt * 8 + tig * 2, kk = h & 15, kstep = h >> 4;
            int tp = ((gid & 7) << 2) | ((kk >> 1) & 3);
            uint hi0, lo0, hi1, lo1;
            split_f16(c.x, c.y, hi0, lo0);   // mrow = gid
            split_f16(c.z, c.w, hi1, lo1);   // mrow = gid + 8
            int base = (((kstep * 2 + mtile) * 32) + tp) * 4;
            int rhib = (kk >> 3) << 1;
            mhi[base + rhib]     = hi0;
            mhi[base + rhib + 1] = hi1;
            mlo[base + rhib]     = lo0;
            mlo[base + rhib + 1] = lo1;
        }
    }
    __syncthreads();

    // (g) L1 weights: h0-part (64 ks) -> sA1, Whh-part (32 ks) -> g_w1h[cta]
    for (int i = tid; i < 32 * 768; i += NTHR) {
        int kp = i % 768, m = i / 768;
        int grow = (m & 3) * 512 + j0 + (m >> 2);
        int k = kp * 2; const float* p;
        if (k < 1024) p = Wih + ((size_t)(2 + d) * 2048 + grow) * 1024 + k;
        else          p = Whh + ((size_t)(2 + d) * 2048 + grow) * 512 + (k - 1024);
        uint packed = pack2(p[0], p[1]);
        int ks = k >> 4, kk = k & 15, mtile = m >> 4, mrow = m & 15;
        int tp  = ((mrow & 7) << 2) | ((kk >> 1) & 3);
        int reg = (mrow >> 3) | ((kk >> 3) << 1);
        if (ks < 64)
            ((uint*)sA1)[((ks * 2 + mtile) * 32 + tp) * 4 + reg] = packed;
        else
            ((uint*)(g_w1h + (size_t)cta * 2048))
                [(((ks - 64) * 2 + mtile) * 32 + tp) * 4 + reg] = packed;
    }

    // (h) biases: bA0 (t=0), bB0 (t>=1, += Wp@bfc), bA1
    float bA0[4] = {0,0,0,0}, bB0[4] = {0,0,0,0}, bA1[4] = {0,0,0,0};
    if (tid < 256) {
        int ul = tid >> 5, j = j0 + ul;
        #pragma unroll
        for (int g = 0; g < 4; ++g) {
            bA0[g] = __ldg(bih + (size_t)d * 2048 + g * 512 + j)
                   + __ldg(bhh + (size_t)d * 2048 + g * 512 + j);
            bA1[g] = __ldg(bih + (size_t)(2 + d) * 2048 + g * 512 + j)
                   + __ldg(bhh + (size_t)(2 + d) * 2048 + g * 512 + j);
            int grow = g * 512 + j;
            const float* wp = Wih + ((size_t)d * 2048 + grow) * 1024 + 512;
            float p = 0.f;
            for (int o = lane; o < 512; o += 32) p += wp[o] * __ldg(bfc + o);
            #pragma unroll
            for (int s = 16; s; s >>= 1) p += __shfl_xor_sync(0xffffffffu, p, s);
            bB0[g] = bA0[g] + p;
        }
    }
    __syncthreads();          // sA1 / sM / g_w1h(own) ready

    // ================= main autoregressive loop ==============================
    float creg0 = 0.f, hreg0 = 0.f, creg1 = 0.f, hreg1 = 0.f;
    const int mtile = wrp & 1;
    const int piece = wrp >> 1;
    const uint4* Mlo = g_Mlo + (size_t)cta * 4096;
    const uint4* W1h = g_w1h + (size_t)cta * 2048;

    for (int t = 0; t < 512; ++t) {
        const int pold = t & 1, pnew = pold ^ 1;
        const uint2* histT = g_h1hist + (size_t)t * 2 * SEG_U2;

        // ---- L0: gates = Wx@x + M@h1cat(t-1) + Wh0@h0(t-1) ----
        {
            Acc c0={0,0,0,0}, c1={0,0,0,0}, c2={0,0,0,0}, c3={0,0,0,0};
            if (piece == 0 || piece == 5) {
                if (piece == 5) warp_wait(&g_cnt0, 128u * (uint)t);
                const uint4* A = sA0 + ((piece == 0 ? 0 : 64) + mtile) * 32 + lane;
                const uint2* B = (piece == 0)
                    ? g_xfrag + (size_t)t * SEG_U2 + lane
                    : g_h0frag + (size_t)(pold * 2 + d) * SEG_U2 + lane;
                #pragma unroll 8
                for (int k = 0; k < 32; ++k) {
                    uint2 v0 = __ldcg(B + k * 32);
                    uint2 v1 = __ldcg(B + k * 32 + 1024);
                    uint2 v2 = __ldcg(B + k * 32 + 2048);
                    uint2 v3 = __ldcg(B + k * 32 + 3072);
                    uint4 a  = A[k * 64];
                    mma_f16(c0, a, v0.x, v0.y);
                    mma_f16(c1, a, v1.x, v1.y);
                    mma_f16(c2, a, v2.x, v2.y);
                    mma_f16(c3, a, v3.x, v3.y);
                }
            } else {
                warp_wait(&g_cnt1, 128u * (uint)t);
                const int km0 = (piece - 1) * 16;
                const uint4* Ah = sM  + (km0 * 2 + mtile) * 32 + lane;
                const uint4* Al = Mlo + (km0 * 2 + mtile) * 32 + lane;
                const uint2* B  = histT + (size_t)(km0 >> 5) * SEG_U2
                                + (km0 & 31) * 32 + lane;
                #pragma unroll 4
                for (int k = 0; k < 16; ++k) {
                    uint2 v0 = __ldcg(B + k * 32);
                    uint2 v1 = __ldcg(B + k * 32 + 1024);
                    uint2 v2 = __ldcg(B + k * 32 + 2048);
                    uint2 v3 = __ldcg(B + k * 32 + 3072);
                    uint4 ah = Ah[k * 64];
                    uint4 al = __ldg(Al + k * 64);
                    mma_f16(c0, ah, v0.x, v0.y);
                    mma_f16(c1, ah, v1.x, v1.y);
                    mma_f16(c2, ah, v2.x, v2.y);
                    mma_f16(c3, ah, v3.x, v3.y);
                    mma_f16(c0, al, v0.x, v0.y);
                    mma_f16(c1, al, v1.x, v1.y);
                    mma_f16(c2, al, v2.x, v2.y);
                    mma_f16(c3, al, v3.x, v3.y);
                }
            }
            const int gid = lane >> 2, tig = lane & 3;
            float* r = sR + piece * 1056;
            const int m0 = mtile * 16 + gid;
            stacc1(r, m0, 0  + tig * 2, c0);
            stacc1(r, m0, 8  + tig * 2, c1);
            stacc1(r, m0, 16 + tig * 2, c2);
            stacc1(r, m0, 24 + tig * 2, c3);
            __syncthreads();
            if (tid < 256)
                pointwise(sR, t == 0 ? bA0 : bB0, creg0, hreg0,
                          g_h0frag + (size_t)(pnew * 2 + d) * SEG_U2, j0);
            publish(&g_cnt0);
        }

        // ---- L1: gates = W@[h0f|h0b] + Whh@h1(t-1) ----
        {
            Acc c0={0,0,0,0}, c1={0,0,0,0}, c2={0,0,0,0}, c3={0,0,0,0};
            if (piece < 4) {
                warp_wait(&g_cnt0, 128u * (uint)(t + 1));
                const uint2* B = g_h0frag
                    + (size_t)(pnew * 2 + (piece >> 1)) * SEG_U2
                    + ((piece & 1) * 16) * 32 + lane;
                const uint4* A = sA1 + ((piece * 16) * 2 + mtile) * 32 + lane;
                #pragma unroll 8
                for (int k = 0; k < 16; ++k) {
                    uint2 v0 = __ldcg(B + k * 32);
                    uint2 v1 = __ldcg(B + k * 32 + 1024);
                    uint2 v2 = __ldcg(B + k * 32 + 2048);
                    uint2 v3 = __ldcg(B + k * 32 + 3072);
                    uint4 a  = A[k * 64];
                    mma_f16(c0, a, v0.x, v0.y);
                    mma_f16(c1, a, v1.x, v1.y);
                    mma_f16(c2, a, v2.x, v2.y);
                    mma_f16(c3, a, v3.x, v3.y);
                }
            } else {
                if (piece == 5) warp_wait(&g_cnt1, 128u * (uint)t);
                const int ks0 = (piece - 4) * 16;
                const uint2* B = histT + (size_t)d * SEG_U2 + ks0 * 32 + lane;
                const uint4* A = W1h + (ks0 * 2 + mtile) * 32 + lane;
                #pragma unroll 8
                for (int k = 0; k < 16; ++k) {
                    uint2 v0 = __ldcg(B + k * 32);
                    uint2 v1 = __ldcg(B + k * 32 + 1024);
                    uint2 v2 = __ldcg(B + k * 32 + 2048);
                    uint2 v3 = __ldcg(B + k * 32 + 3072);
                    uint4 a  = __ldg(A + k * 64);
                    mma_f16(c0, a, v0.x, v0.y);
                    mma_f16(c1, a, v1.x, v1.y);
                    mma_f16(c2, a, v2.x, v2.y);
                    mma_f16(c3, a, v3.x, v3.y);
                }
            }
            const int gid = lane >> 2, tig = lane & 3;
            float* r = sR + piece * 1056;
            const int m0 = mtile * 16 + gid;
            stacc1(r, m0, 0  + tig * 2, c0);
            stacc1(r, m0, 8  + tig * 2, c1);
            stacc1(r, m0, 16 + tig * 2, c2);
            stacc1(r, m0, 24 + tig * 2, c3);
            __syncthreads();
            if (tid < 256)
                pointwise(sR, bA1, creg1, hreg1,
                          g_h1hist + ((size_t)(t + 1) * 2 + d) * SEG_U2, j0);
            publish(&g_cnt1);
        }
    }

    // ================= epilogue: h_n, c_n from registers =====================
    if (tid < 256) {
        const size_t HN = 8388608ull;             // 32*512*512
        const size_t CN = HN + 65536ull;
        int ul = tid >> 5, b = tid & 31;
        int j = j0 + ul;
        out[HN + ((size_t)((0 + d) * 32 + b)) * 512 + j] = hreg0;
        out[HN + ((size_t)((2 + d) * 32 + b)) * 512 + j] = hreg1;
        out[CN + ((size_t)((0 + d) * 32 + b)) * 512 + j] = creg0;
        out[CN + ((size_t)((2 + d) * 32 + b)) * 512 + j] = creg1;
    }

    // ================= batched FC over all t =================================
    if (tid == 0) {                      // wait for ALL h1 history
        unsigned v;
        do {
            asm volatile("ld.acquire.gpu.u32 %0, [%1];"
                         : "=r"(v) : "l"(&g_cnt1) : "memory");
        } while ((int)(v - 65536u) < 0);
    }
    __syncthreads();
    {
        float* sRw = sR + wrp * 528;                 // [16][33] per warp
        for (int tt = 0; tt < 4; ++tt) {
            const int t = cta + tt * 128;
            const uint2* Bbase = g_h1hist + (size_t)(t + 1) * 2 * SEG_U2;
            for (int rb = wrp; rb < 32; rb += 12) {
                const uint4* A = g_afc + (size_t)(rb * 64) * 32 + lane;
                Acc c0={0,0,0,0}, c1={0,0,0,0}, c2={0,0,0,0}, c3={0,0,0,0};
                #pragma unroll 4
                for (int ks = 0; ks < 64; ++ks) {
                    const uint2* B = Bbase + (size_t)(ks >> 5) * SEG_U2
                                   + (ks & 31) * 32 + lane;
                    uint2 v0 = __ldcg(B);
                    uint2 v1 = __ldcg(B + 1024);
                    uint2 v2 = __ldcg(B + 2048);
                    uint2 v3 = __ldcg(B + 3072);
                    uint4 a  = __ldg(A + ks * 32);
                    mma_f16(c0, a, v0.x, v0.y);
                    mma_f16(c1, a, v1.x, v1.y);
                    mma_f16(c2, a, v2.x, v2.y);
                    mma_f16(c3, a, v3.x, v3.y);
                }
                const int gid = lane >> 2, tig = lane & 3;
                stacc1(sRw, gid, 0  + tig * 2, c0);
                stacc1(sRw, gid, 8  + tig * 2, c1);
                stacc1(sRw, gid, 16 + tig * 2, c2);
                stacc1(sRw, gid, 24 + tig * 2, c3);
                __syncwarp();
                float* op = out + ((size_t)lane * 512 + t) * 512 + rb * 16;
                #pragma unroll
                for (int q = 0; q < 4; ++q) {
                    float v0 = sRw[(q*4+0) * 33 + lane] + __ldg(bfc + rb*16 + q*4+0);
                    float v1 = sRw[(q*4+1) * 33 + lane] + __ldg(bfc + rb*16 + q*4+1);
                    float v2 = sRw[(q*4+2) * 33 + lane] + __ldg(bfc + rb*16 + q*4+2);
                    float v3 = sRw[(q*4+3) * 33 + lane] + __ldg(bfc + rb*16 + q*4+3);
                    *(float4*)(op + q * 4) = make_float4(v0, v1, v2, v3);
                }
                __syncwarp();
            }
        }
    }

    // ================= reset dataflow counters for next launch ===============
    gridbar();
    if (cta == 0 && tid == 0) {
        asm volatile("st.relaxed.gpu.u32 [%0], %1;" :: "l"(&g_cnt0), "r"(0u) : "memory");
        asm volatile("st.relaxed.gpu.u32 [%0], %1;" :: "l"(&g_cnt1), "r"(0u) : "memory");
    }
}

extern "C" void kernel_launch(void* const* d_in, const int* in_sizes, int n_in,
                              void* d_out, int out_size) {
    (void)in_sizes; (void)n_in; (void)out_size;
    const float* x   = (const float*)d_in[0];
    const float* Wih = (const float*)d_in[2];
    const float* Whh = (const float*)d_in[3];
    const float* bih = (const float*)d_in[4];
    const float* bhh = (const float*)d_in[5];
    const float* Wfc = (const float*)d_in[6];
    const float* bfc = (const float*)d_in[7];
    cudaFuncSetAttribute(ar_encoder_v7,
                         cudaFuncAttributeMaxDynamicSharedMemorySize, SMEM_BYTES);
    ar_encoder_v7<<<NCTA, NTHR, SMEM_BYTES>>>(x, Wih, Whh, bih, bhh, Wfc, bfc,
                                              (float*)d_out);
}

// round 8
// speedup vs baseline: 3.9782x; 1.2248x over previous
#include <cuda_runtime.h>
#include <cuda_fp16.h>

typedef unsigned int uint;
typedef unsigned short ushort;

#define NTHR 384
#define NCTA 128
#define SEG_U2 4096u            // B segment (K=512): [4 nt][32 ks][32 lane] uint2

// SMEM layout (bytes)
#define SA0_OFF 0               // L0 x+h0 weights [64 ks][2 mt][32 ln] uint4 = 65536
#define SA1_OFF 65536           // L1 h0f+h0b weights [64 ks][2 mt][32 ln]   = 65536
#define SM_OFF  131072          // M fragments (fp16) [64 ks][2 mt][32 ln]   = 65536
#define SR_OFF  196608          // reduce buffer 6336 floats                 = 25344
#define SMEM_BYTES (196608 + 25344)

// Static device scratch (allocation-free)
__device__ uint2 g_xfrag[512u * SEG_U2];          // x B-fragments per t (~16MB)
__device__ uint2 g_h0frag[4u * SEG_U2];           // [parity][dir] layer0 h
__device__ uint2 g_h1hist[513ull * 2 * SEG_U2];   // h1cat history [t+1][dir] (~34MB)
__device__ uint4 g_w1h[128ull * 2048];            // per-CTA L1 Whh fragments (4MB)
__device__ uint4 g_afc[32u * 64u * 32u];          // FC A fragments (fp16)
__device__ uint2 g_wfcB[128u * 32u * 32u];        // Wfc B-frags for M build
__device__ unsigned g_arrive = 0, g_release = 0;  // prologue/epilogue barrier
__device__ unsigned g_cnt0 = 0, g_cnt1 = 0;       // dataflow epoch counters

// ---------------- grid barrier (prologue/epilogue only) ----------------------
__device__ __forceinline__ void gridbar() {
    __syncthreads();
    if (threadIdx.x == 0) {
        const unsigned nb = gridDim.x;
        unsigned ticket;
        asm volatile("atom.add.acq_rel.gpu.u32 %0, [%1], %2;"
                     : "=r"(ticket) : "l"(&g_arrive), "r"(1u) : "memory");
        unsigned target = ticket - (ticket % nb) + nb;
        if (ticket % nb == nb - 1u) {
            asm volatile("red.add.release.gpu.u32 [%0], %1;"
                         :: "l"(&g_release), "r"(nb) : "memory");
        } else {
            unsigned rel;
            do {
                asm volatile("ld.acquire.gpu.u32 %0, [%1];"
                             : "=r"(rel) : "l"(&g_release) : "memory");
            } while ((int)(rel - target) < 0);
        }
    }
    __syncthreads();
}

// per-warp dataflow wait with backoff: lane0 acquires counter, warp joins
__device__ __forceinline__ void warp_wait(unsigned* cnt, unsigned tgt) {
    if ((threadIdx.x & 31) == 0) {
        unsigned v;
        for (;;) {
            asm volatile("ld.acquire.gpu.u32 %0, [%1];"
                         : "=r"(v) : "l"(cnt) : "memory");
            if ((int)(v - tgt) >= 0) break;
            __nanosleep(40);
        }
    }
    __syncwarp();
}

// CTA publish: all writers fence, then one release-increment
__device__ __forceinline__ void publish(unsigned* cnt) {
    __threadfence();
    __syncthreads();
    if (threadIdx.x == 0)
        asm volatile("red.add.release.gpu.u32 [%0], %1;"
                     :: "l"(cnt), "r"(1u) : "memory");
}

// ---------------- fast activations -------------------------------------------
__device__ __forceinline__ float sigf(float v) {
    return __fdividef(1.f, 1.f + __expf(-v));
}
__device__ __forceinline__ float tanhf_fast(float v) {
    float vc = fminf(fmaxf(v, -15.f), 15.f);
    float e  = __expf(-2.f * vc);
    return __fdividef(1.f - e, 1.f + e);
}

__device__ __forceinline__ uint pack2(float a, float b) {
    __half2 h = __floats2half2_rn(a, b);
    return *reinterpret_cast<uint*>(&h);
}

// Write one fp16 activation (k, n) into B-fragment layout.
__device__ __forceinline__ void write_hfrag(uint2* seg, int k, int n, float v) {
    ushort h = __half_as_ushort(__float2half_rn(v));
    int ks = k >> 4, kk = k & 15, nt = n >> 3;
    int tp  = ((n & 7) << 2) | ((kk >> 1) & 3);
    int reg = kk >> 3, hf = kk & 1;
    ushort* p = (ushort*)(seg + (size_t)(nt * 32 + ks) * 32 + tp);
    p[reg * 2 + hf] = h;
}

// ---------------- mma.sync m16n8k16 fp16 -> fp32 ------------------------------
struct Acc { float x, y, z, w; };

__device__ __forceinline__ void mma_f16(Acc& c, uint4 a, uint b0, uint b1) {
    asm volatile(
        "mma.sync.aligned.m16n8k16.row.col.f32.f16.f16.f32 "
        "{%0,%1,%2,%3}, {%4,%5,%6,%7}, {%8,%9}, {%0,%1,%2,%3};"
        : "+f"(c.x), "+f"(c.y), "+f"(c.z), "+f"(c.w)
        : "r"(a.x), "r"(a.y), "r"(a.z), "r"(a.w), "r"(b0), "r"(b1));
}

__device__ __forceinline__ void stacc1(float* r, int m0, int n0, Acc a) {
    r[m0 * 33 + n0]           = a.x;
    r[m0 * 33 + n0 + 1]       = a.y;
    r[(m0 + 8) * 33 + n0]     = a.z;
    r[(m0 + 8) * 33 + n0 + 1] = a.w;
}

// store 4 tiles (2 mtiles x 2 ntiles) of one warp into sR[piece]
__device__ __forceinline__ void stacc4(float* r, int npair, int lane,
                                       Acc c00, Acc c01, Acc c10, Acc c11) {
    const int gid = lane >> 2, tig = lane & 3;
    const int nb  = npair * 16 + tig * 2;
    stacc1(r, gid,      nb,     c00);
    stacc1(r, gid,      nb + 8, c01);
    stacc1(r, 16 + gid, nb,     c10);
    stacc1(r, 16 + gid, nb + 8, c11);
}

// gate reduce + LSTM pointwise for first 256 threads
__device__ __forceinline__ void pointwise(const float* sR, const float* b4,
                                          float& creg, float& hreg,
                                          uint2* hout, int j0)
{
    const int tid = threadIdx.x;
    const int ul = tid >> 5, b = tid & 31;
    const int j = j0 + ul;
    float g4[4];
    #pragma unroll
    for (int g = 0; g < 4; ++g) {
        int m = ul * 4 + g;
        float s = b4[g];
        #pragma unroll
        for (int p = 0; p < 6; ++p) s += sR[p * 1056 + m * 33 + b];
        g4[g] = s;
    }
    float cc = sigf(g4[1]) * creg + sigf(g4[0]) * tanhf_fast(g4[2]);
    creg = cc;
    hreg = sigf(g4[3]) * tanhf_fast(cc);
    write_hfrag(hout, j, b, hreg);
}

// -----------------------------------------------------------------------------
extern "C" __global__ void __launch_bounds__(NTHR, 1)
ar_encoder_v8(const float* __restrict__ x,     // [32,512,512]
              const float* __restrict__ Wih,   // [4][2048][1024]
              const float* __restrict__ Whh,   // [4][2048][512]
              const float* __restrict__ bih,   // [4][2048]
              const float* __restrict__ bhh,   // [4][2048]
              const float* __restrict__ Wfc,   // [512][1024]
              const float* __restrict__ bfc,   // [512]
              float* __restrict__ out)
{
    extern __shared__ char smem[];
    uint4* sA0 = (uint4*)(smem + SA0_OFF);
    uint4* sA1 = (uint4*)(smem + SA1_OFF);
    uint4* sM  = (uint4*)(smem + SM_OFF);
    float* sR  = (float*)(smem + SR_OFF);

    const int tid  = threadIdx.x;
    const int cta  = blockIdx.x;
    const int lane = tid & 31;
    const int wrp  = tid >> 5;
    const int gsz  = NCTA * NTHR;
    const int gtid = cta * NTHR + tid;

    const int d    = cta >> 6;
    const int ublk = cta & 63;
    const int j0   = ublk * 8;

    // ================= prologue phase 1 =====================================
    // (a) L0 weights (Wx + Wh0) -> sA0
    for (int i = tid; i < 32 * 512; i += NTHR) {
        int kp = i & 511, m = i >> 9;
        int grow = (m & 3) * 512 + j0 + (m >> 2);
        int k, ks; const float* p;
        if (kp < 256) { k = kp * 2; ks = k >> 4;
                        p = Wih + ((size_t)d * 2048 + grow) * 1024 + k; }
        else          { k = (kp - 256) * 2; ks = 32 + (k >> 4);
                        p = Whh + ((size_t)d * 2048 + grow) * 512 + k; }
        uint packed = pack2(p[0], p[1]);
        int kk = k & 15, mtile = m >> 4, mrow = m & 15;
        int tp  = ((mrow & 7) << 2) | ((kk >> 1) & 3);
        int reg = (mrow >> 3) | ((kk >> 3) << 1);
        ((uint*)sA0)[((ks * 2 + mtile) * 32 + tp) * 4 + reg] = packed;
    }
    // (b) Wp (prev-columns of Wih layer0) -> sA1 as TEMP A-fragments (K=512)
    for (int i = tid; i < 32 * 256; i += NTHR) {
        int kp = i & 255, m = i >> 8;
        int grow = (m & 3) * 512 + j0 + (m >> 2);
        int k = kp * 2;
        const float* p = Wih + ((size_t)d * 2048 + grow) * 1024 + 512 + k;
        uint packed = pack2(p[0], p[1]);
        int ks = k >> 4, kk = k & 15, mtile = m >> 4, mrow = m & 15;
        int tp  = ((mrow & 7) << 2) | ((kk >> 1) & 3);
        int reg = (mrow >> 3) | ((kk >> 3) << 1);
        ((uint*)sA1)[((ks * 2 + mtile) * 32 + tp) * 4 + reg] = packed;
    }
    // (c) Wfc -> B-fragments for the M GEMM (grid-strided)
    for (uint i = gtid; i < 128u * 32u * 32u; i += gsz) {
        int ln = (int)(i & 31), ks = (int)((i >> 5) & 31), nt = (int)(i >> 10);
        int n  = nt * 8 + (ln >> 2);
        int o0 = ks * 16 + (ln & 3) * 2;
        uint2 v;
        v.x = pack2(Wfc[(size_t)o0 * 1024 + n],       Wfc[(size_t)(o0 + 1) * 1024 + n]);
        v.y = pack2(Wfc[(size_t)(o0 + 8) * 1024 + n], Wfc[(size_t)(o0 + 9) * 1024 + n]);
        g_wfcB[i] = v;
    }
    // (d) FC weights -> fp16 A fragments
    for (uint i = gtid; i < 512u * 512u; i += gsz) {
        int kp = (int)(i & 511u), row = (int)(i >> 9);
        int k = kp * 2;
        const float* p = Wfc + ((size_t)row << 10) + k;
        uint packed = pack2(p[0], p[1]);
        int rowblk = row >> 4, mrow = row & 15;
        int kstep = k >> 4, kk = k & 15;
        int tp  = ((mrow & 7) << 2) | ((kk >> 1) & 3);
        int reg = (mrow >> 3) | ((kk >> 3) << 1);
        ((uint*)g_afc)[(((rowblk * 64 + kstep) * 32) + tp) * 4 + reg] = packed;
    }
    // (e) input x -> fp16 B fragments, all t
    for (uint s = gtid; s < 512u * SEG_U2; s += gsz) {
        int ln = (int)(s & 31), ks = (int)((s >> 5) & 31), nt = (int)((s >> 10) & 3);
        int t  = (int)(s >> 12);
        int tig = ln & 3, gid = ln >> 2;
        int n = nt * 8 + gid, k0 = ks * 16 + tig * 2;
        const float* xp = x + ((size_t)n * 512 + t) * 512 + k0;
        uint2 v;
        v.x = pack2(xp[0], xp[1]);
        v.y = pack2(xp[8], xp[9]);
        g_xfrag[s] = v;
    }
    // (f) zero h0frag (both parities) + hist[0]
    {
        uint2 z = make_uint2(0, 0);
        for (uint i = gtid; i < 6u * SEG_U2; i += gsz) {
            if (i < 4u * SEG_U2) g_h0frag[i] = z;
            else                 g_h1hist[i - 4u * SEG_U2] = z;
        }
    }
    gridbar();   // wfcB / xfrag / zeros / afc visible everywhere

    // ================= prologue phase 2: M = Wp @ Wfc (fp16, hi only) =======
    {
        const int mtile = wrp & 1;
        uint* mhi = (uint*)sM;
        for (int nt = (wrp >> 1); nt < 128; nt += 6) {
            Acc c = {0, 0, 0, 0};
            const uint2* B = g_wfcB + (size_t)nt * 1024 + lane;
            const uint4* A = sA1 + mtile * 32 + lane;
            #pragma unroll 8
            for (int ks = 0; ks < 32; ++ks) {
                uint2 v = __ldcg(B + ks * 32);
                uint4 a = A[ks * 64];
                mma_f16(c, a, v.x, v.y);
            }
            int gid = lane >> 2, tig = lane & 3;
            int h = nt * 8 + tig * 2, kk = h & 15, kstep = h >> 4;
            int tp = ((gid & 7) << 2) | ((kk >> 1) & 3);
            int base = (((kstep * 2 + mtile) * 32) + tp) * 4;
            int rhib = (kk >> 3) << 1;
            mhi[base + rhib]     = pack2(c.x, c.y);   // mrow = gid
            mhi[base + rhib + 1] = pack2(c.z, c.w);   // mrow = gid + 8
        }
    }
    __syncthreads();

    // (g) L1 weights: h0-part (64 ks) -> sA1, Whh-part (32 ks) -> g_w1h[cta]
    for (int i = tid; i < 32 * 768; i += NTHR) {
        int kp = i % 768, m = i / 768;
        int grow = (m & 3) * 512 + j0 + (m >> 2);
        int k = kp * 2; const float* p;
        if (k < 1024) p = Wih + ((size_t)(2 + d) * 2048 + grow) * 1024 + k;
        else          p = Whh + ((size_t)(2 + d) * 2048 + grow) * 512 + (k - 1024);
        uint packed = pack2(p[0], p[1]);
        int ks = k >> 4, kk = k & 15, mtile = m >> 4, mrow = m & 15;
        int tp  = ((mrow & 7) << 2) | ((kk >> 1) & 3);
        int reg = (mrow >> 3) | ((kk >> 3) << 1);
        if (ks < 64)
            ((uint*)sA1)[((ks * 2 + mtile) * 32 + tp) * 4 + reg] = packed;
        else
            ((uint*)(g_w1h + (size_t)cta * 2048))
                [(((ks - 64) * 2 + mtile) * 32 + tp) * 4 + reg] = packed;
    }

    // (h) biases: bA0 (t=0), bB0 (t>=1, += Wp@bfc), bA1
    float bA0[4] = {0,0,0,0}, bB0[4] = {0,0,0,0}, bA1[4] = {0,0,0,0};
    if (tid < 256) {
        int ul = tid >> 5, j = j0 + ul;
        #pragma unroll
        for (int g = 0; g < 4; ++g) {
            bA0[g] = __ldg(bih + (size_t)d * 2048 + g * 512 + j)
                   + __ldg(bhh + (size_t)d * 2048 + g * 512 + j);
            bA1[g] = __ldg(bih + (size_t)(2 + d) * 2048 + g * 512 + j)
                   + __ldg(bhh + (size_t)(2 + d) * 2048 + g * 512 + j);
            int grow = g * 512 + j;
            const float* wp = Wih + ((size_t)d * 2048 + grow) * 1024 + 512;
            float p = 0.f;
            for (int o = lane; o < 512; o += 32) p += wp[o] * __ldg(bfc + o);
            #pragma unroll
            for (int s = 16; s; s >>= 1) p += __shfl_xor_sync(0xffffffffu, p, s);
            bB0[g] = bA0[g] + p;
        }
    }
    __syncthreads();          // sA1 / sM / g_w1h(own) ready

    // ================= main autoregressive loop ==============================
    float creg0 = 0.f, hreg0 = 0.f, creg1 = 0.f, hreg1 = 0.f;
    const int npair = wrp & 1;           // covers ntiles 2*npair, 2*npair+1
    const int piece = wrp >> 1;          // 0..5
    const int nb    = npair * 2048;      // B offset for first ntile
    const uint4* W1h = g_w1h + (size_t)cta * 2048;

    for (int t = 0; t < 512; ++t) {
        const int pold = t & 1, pnew = pold ^ 1;
        const uint2* histT = g_h1hist + (size_t)t * 2 * SEG_U2;

        // ---- L0: gates = Wx@x + M@h1cat(t-1) + Wh0@h0(t-1) ----
        {
            Acc c00={0,0,0,0}, c01={0,0,0,0}, c10={0,0,0,0}, c11={0,0,0,0};
            if (piece == 0 || piece == 5) {
                if (piece == 5) warp_wait(&g_cnt0, 128u * (uint)t);
                const uint4* A = sA0 + (piece == 0 ? 0 : 2048) + lane;
                const uint2* B = (piece == 0)
                    ? g_xfrag + (size_t)t * SEG_U2 + nb + lane
                    : g_h0frag + (size_t)(pold * 2 + d) * SEG_U2 + nb + lane;
                #pragma unroll 8
                for (int k = 0; k < 32; ++k) {
                    uint2 v0 = __ldcg(B + k * 32);
                    uint2 v1 = __ldcg(B + k * 32 + 1024);
                    uint4 a0 = A[k * 64];
                    uint4 a1 = A[k * 64 + 32];
                    mma_f16(c00, a0, v0.x, v0.y);
                    mma_f16(c01, a0, v1.x, v1.y);
                    mma_f16(c10, a1, v0.x, v0.y);
                    mma_f16(c11, a1, v1.x, v1.y);
                }
            } else {
                warp_wait(&g_cnt1, 128u * (uint)t);
                const int km0 = (piece - 1) * 16;
                const uint4* A = sM + km0 * 64 + lane;
                const uint2* B = histT + (size_t)(km0 >> 5) * SEG_U2
                               + (km0 & 31) * 32 + nb + lane;
                #pragma unroll 8
                for (int k = 0; k < 16; ++k) {
                    uint2 v0 = __ldcg(B + k * 32);
                    uint2 v1 = __ldcg(B + k * 32 + 1024);
                    uint4 a0 = A[k * 64];
                    uint4 a1 = A[k * 64 + 32];
                    mma_f16(c00, a0, v0.x, v0.y);
                    mma_f16(c01, a0, v1.x, v1.y);
                    mma_f16(c10, a1, v0.x, v0.y);
                    mma_f16(c11, a1, v1.x, v1.y);
                }
            }
            stacc4(sR + piece * 1056, npair, lane, c00, c01, c10, c11);
            __syncthreads();
            if (tid < 256)
                pointwise(sR, t == 0 ? bA0 : bB0, creg0, hreg0,
                          g_h0frag + (size_t)(pnew * 2 + d) * SEG_U2, j0);
            publish(&g_cnt0);
        }

        // ---- L1: gates = W@[h0f|h0b] + Whh@h1(t-1) ----
        {
            Acc c00={0,0,0,0}, c01={0,0,0,0}, c10={0,0,0,0}, c11={0,0,0,0};
            if (piece < 4) {
                warp_wait(&g_cnt0, 128u * (uint)(t + 1));
                const uint2* B = g_h0frag
                    + (size_t)(pnew * 2 + (piece >> 1)) * SEG_U2
                    + ((piece & 1) * 16) * 32 + nb + lane;
                const uint4* A = sA1 + (piece * 16) * 64 + lane;
                #pragma unroll 8
                for (int k = 0; k < 16; ++k) {
                    uint2 v0 = __ldcg(B + k * 32);
                    uint2 v1 = __ldcg(B + k * 32 + 1024);
                    uint4 a0 = A[k * 64];
                    uint4 a1 = A[k * 64 + 32];
                    mma_f16(c00, a0, v0.x, v0.y);
                    mma_f16(c01, a0, v1.x, v1.y);
                    mma_f16(c10, a1, v0.x, v0.y);
                    mma_f16(c11, a1, v1.x, v1.y);
                }
            } else {
                if (piece == 5) warp_wait(&g_cnt1, 128u * (uint)t);
                const int ks0 = (piece - 4) * 16;
                const uint2* B = histT + (size_t)d * SEG_U2 + ks0 * 32 + nb + lane;
                const uint4* A = W1h + ks0 * 64 + lane;
                #pragma unroll 8
                for (int k = 0; k < 16; ++k) {
                    uint2 v0 = __ldcg(B + k * 32);
                    uint2 v1 = __ldcg(B + k * 32 + 1024);
                    uint4 a0 = __ldg(A + k * 64);
                    uint4 a1 = __ldg(A + k * 64 + 32);
                    mma_f16(c00, a0, v0.x, v0.y);
                    mma_f16(c01, a0, v1.x, v1.y);
                    mma_f16(c10, a1, v0.x, v0.y);
                    mma_f16(c11, a1, v1.x, v1.y);
                }
            }
            stacc4(sR + piece * 1056, npair, lane, c00, c01, c10, c11);
            __syncthreads();
            if (tid < 256)
                pointwise(sR, bA1, creg1, hreg1,
                          g_h1hist + ((size_t)(t + 1) * 2 + d) * SEG_U2, j0);
            publish(&g_cnt1);
        }
    }

    // ================= epilogue: h_n, c_n from registers =====================
    if (tid < 256) {
        const size_t HN = 8388608ull;             // 32*512*512
        const size_t CN = HN + 65536ull;
        int ul = tid >> 5, b = tid & 31;
        int j = j0 + ul;
        out[HN + ((size_t)((0 + d) * 32 + b)) * 512 + j] = hreg0;
        out[HN + ((size_t)((2 + d) * 32 + b)) * 512 + j] = hreg1;
        out[CN + ((size_t)((0 + d) * 32 + b)) * 512 + j] = creg0;
        out[CN + ((size_t)((2 + d) * 32 + b)) * 512 + j] = creg1;
    }

    // ================= batched FC over all t =================================
    if (tid == 0) {                      // wait for ALL h1 history
        unsigned v;
        for (;;) {
            asm volatile("ld.acquire.gpu.u32 %0, [%1];"
                         : "=r"(v) : "l"(&g_cnt1) : "memory");
            if ((int)(v - 65536u) >= 0) break;
            __nanosleep(80);
        }
    }
    __syncthreads();
    {
        float* sRw = sR + wrp * 528;                 // [16][33] per warp
        for (int tt = 0; tt < 4; ++tt) {
            const int t = cta + tt * 128;
            const uint2* Bbase = g_h1hist + (size_t)(t + 1) * 2 * SEG_U2;
            for (int rb = wrp; rb < 32; rb += 12) {
                const uint4* A = g_afc + (size_t)(rb * 64) * 32 + lane;
                Acc c0={0,0,0,0}, c1={0,0,0,0}, c2={0,0,0,0}, c3={0,0,0,0};
                #pragma unroll 4
                for (int ks = 0; ks < 64; ++ks) {
                    const uint2* B = Bbase + (size_t)(ks >> 5) * SEG_U2
                                   + (ks & 31) * 32 + lane;
                    uint2 v0 = __ldcg(B);
                    uint2 v1 = __ldcg(B + 1024);
                    uint2 v2 = __ldcg(B + 2048);
                    uint2 v3 = __ldcg(B + 3072);
                    uint4 a  = __ldg(A + ks * 32);
                    mma_f16(c0, a, v0.x, v0.y);
                    mma_f16(c1, a, v1.x, v1.y);
                    mma_f16(c2, a, v2.x, v2.y);
                    mma_f16(c3, a, v3.x, v3.y);
                }
                const int gid = lane >> 2, tig = lane & 3;
                stacc1(sRw, gid, 0  + tig * 2, c0);
                stacc1(sRw, gid, 8  + tig * 2, c1);
                stacc1(sRw, gid, 16 + tig * 2, c2);
                stacc1(sRw, gid, 24 + tig * 2, c3);
                __syncwarp();
                float* op = out + ((size_t)lane * 512 + t) * 512 + rb * 16;
                #pragma unroll
                for (int q = 0; q < 4; ++q) {
                    float v0 = sRw[(q*4+0) * 33 + lane] + __ldg(bfc + rb*16 + q*4+0);
                    float v1 = sRw[(q*4+1) * 33 + lane] + __ldg(bfc + rb*16 + q*4+1);
                    float v2 = sRw[(q*4+2) * 33 + lane] + __ldg(bfc + rb*16 + q*4+2);
                    float v3 = sRw[(q*4+3) * 33 + lane] + __ldg(bfc + rb*16 + q*4+3);
                    *(float4*)(op + q * 4) = make_float4(v0, v1, v2, v3);
                }
                __syncwarp();
            }
        }
    }

    // ================= reset dataflow counters for next launch ===============
    gridbar();
    if (cta == 0 && tid == 0) {
        asm volatile("st.relaxed.gpu.u32 [%0], %1;" :: "l"(&g_cnt0), "r"(0u) : "memory");
        asm volatile("st.relaxed.gpu.u32 [%0], %1;" :: "l"(&g_cnt1), "r"(0u) : "memory");
    }
}

extern "C" void kernel_launch(void* const* d_in, const int* in_sizes, int n_in,
                              void* d_out, int out_size) {
    (void)in_sizes; (void)n_in; (void)out_size;
    const float* x   = (const float*)d_in[0];
    const float* Wih = (const float*)d_in[2];
    const float* Whh = (const float*)d_in[3];
    const float* bih = (const float*)d_in[4];
    const float* bhh = (const float*)d_in[5];
    const float* Wfc = (const float*)d_in[6];
    const float* bfc = (const float*)d_in[7];
    cudaFuncSetAttribute(ar_encoder_v8,
                         cudaFuncAttributeMaxDynamicSharedMemorySize, SMEM_BYTES);
    ar_encoder_v8<<<NCTA, NTHR, SMEM_BYTES>>>(x, Wih, Whh, bih, bhh, Wfc, bfc,
                                              (float*)d_out);
}